// round 1
// baseline (speedup 1.0000x reference)
#include <cuda_runtime.h>
#include <math.h>

#define T_TOK 4096
#define HIDD  2048
#define NH    16
#define HD    128
#define SEQ   2048
#define NB    2
#define NE    8
#define INTER 4096
#define CAP   4096
#define EPS   1e-5f

// ---------------- scratch (__device__ globals: allocation-free) ----------------
__device__ float g_xn1[(size_t)T_TOK * HIDD];
__device__ float g_q  [(size_t)T_TOK * HIDD];
__device__ float g_k  [(size_t)T_TOK * HIDD];
__device__ float g_v  [(size_t)T_TOK * HIDD];
__device__ float g_att[(size_t)T_TOK * HIDD];
__device__ float g_x2 [(size_t)T_TOK * HIDD];
__device__ float g_xn2[(size_t)T_TOK * HIDD];
__device__ float g_hg [(size_t)NE * CAP * INTER];
__device__ float g_hu [(size_t)NE * CAP * INTER];
__device__ float g_yb [(size_t)NE * CAP * HIDD];
__device__ int    g_cnt[NE];
__device__ int    g_gather[NE * CAP];
__device__ int2   g_slots[T_TOK];
__device__ float2 g_wts[T_TOK];

// ---------------- RMSNorm ----------------
__global__ void rmsnorm_k(const float* __restrict__ x, const float* __restrict__ w,
                          float* __restrict__ y) {
    int tok = blockIdx.x;
    const float* xr = x + (size_t)tok * HIDD;
    float s = 0.f;
    for (int i = threadIdx.x * 4; i < HIDD; i += blockDim.x * 4) {
        float4 v = *(const float4*)(xr + i);
        s += v.x * v.x + v.y * v.y + v.z * v.z + v.w * v.w;
    }
    __shared__ float red[32];
    for (int o = 16; o > 0; o >>= 1) s += __shfl_xor_sync(0xffffffffu, s, o);
    if ((threadIdx.x & 31) == 0) red[threadIdx.x >> 5] = s;
    __syncthreads();
    if (threadIdx.x < 32) {
        float v = (threadIdx.x < (blockDim.x >> 5)) ? red[threadIdx.x] : 0.f;
        for (int o = 4; o > 0; o >>= 1) v += __shfl_xor_sync(0xffffffffu, v, o);
        if (threadIdx.x == 0) red[0] = rsqrtf(v / (float)HIDD + EPS);
    }
    __syncthreads();
    float sc = red[0];
    float* yr = y + (size_t)tok * HIDD;
    for (int i = threadIdx.x * 4; i < HIDD; i += blockDim.x * 4) {
        float4 v = *(const float4*)(xr + i);
        float4 wv = *(const float4*)(w + i);
        float4 o;
        o.x = v.x * sc * wv.x; o.y = v.y * sc * wv.y;
        o.z = v.z * sc * wv.z; o.w = v.w * sc * wv.w;
        *(float4*)(yr + i) = o;
    }
}

// ---------------- generic fp32 GEMM core: C[M,N] = A[M,K] @ B[N,K]^T ----------------
#define BM 128
#define BN 128
#define BK 8

__device__ __forceinline__ void gemm_core(const float* __restrict__ aptr,
                                          const float* __restrict__ bptr,
                                          bool aval, bool bval, int K,
                                          float (&acc)[8][8]) {
    __shared__ float As[BK][BM + 4];
    __shared__ float Bs[BK][BN + 4];
    const int t = threadIdx.x;
    const int lr = t >> 1;
    const int lc = (t & 1) * 4;
    const int tx = t & 15;
    const int ty = t >> 4;
    for (int k0 = 0; k0 < K; k0 += BK) {
        float4 av = make_float4(0.f, 0.f, 0.f, 0.f);
        float4 bv = make_float4(0.f, 0.f, 0.f, 0.f);
        if (aval) av = *(const float4*)(aptr + k0 + lc);
        if (bval) bv = *(const float4*)(bptr + k0 + lc);
        As[lc + 0][lr] = av.x; As[lc + 1][lr] = av.y;
        As[lc + 2][lr] = av.z; As[lc + 3][lr] = av.w;
        Bs[lc + 0][lr] = bv.x; Bs[lc + 1][lr] = bv.y;
        Bs[lc + 2][lr] = bv.z; Bs[lc + 3][lr] = bv.w;
        __syncthreads();
#pragma unroll
        for (int kk = 0; kk < BK; kk++) {
            float a[8], b[8];
#pragma unroll
            for (int i = 0; i < 8; i++) a[i] = As[kk][ty + 16 * i];
#pragma unroll
            for (int j = 0; j < 8; j++) b[j] = Bs[kk][tx + 16 * j];
#pragma unroll
            for (int i = 0; i < 8; i++)
#pragma unroll
                for (int j = 0; j < 8; j++) acc[i][j] += a[i] * b[j];
        }
        __syncthreads();
    }
}

__global__ void sgemm_tn(const float* __restrict__ A, const float* __restrict__ B,
                         const float* __restrict__ resid, float* __restrict__ C,
                         int M, int N, int K) {
    const int t = threadIdx.x;
    const int lr = t >> 1;
    const int bm = blockIdx.y * BM, bn = blockIdx.x * BN;
    bool aval = (bm + lr) < M;
    bool bval = (bn + lr) < N;
    const float* aptr = A + (size_t)(aval ? bm + lr : 0) * K;
    const float* bptr = B + (size_t)(bval ? bn + lr : 0) * K;
    float acc[8][8];
#pragma unroll
    for (int i = 0; i < 8; i++)
#pragma unroll
        for (int j = 0; j < 8; j++) acc[i][j] = 0.f;
    gemm_core(aptr, bptr, aval, bval, K, acc);
    const int tx = t & 15, ty = t >> 4;
#pragma unroll
    for (int i = 0; i < 8; i++) {
        int r = bm + ty + 16 * i;
        if (r >= M) continue;
#pragma unroll
        for (int j = 0; j < 8; j++) {
            int c = bn + tx + 16 * j;
            if (c < N) {
                float v = acc[i][j];
                if (resid) v += resid[(size_t)r * N + c];
                C[(size_t)r * N + c] = v;
            }
        }
    }
}

// ---------------- MoE GEMMs ----------------
// gate/up: Out[e, m, :INTER] = X[gather[e,m], :] @ W[e]^T
__global__ void moe_gemm_gu(const float* __restrict__ X, const float* __restrict__ W,
                            float* __restrict__ Out) {
    const int e = blockIdx.z;
    int M = g_cnt[e];
    const int bm = blockIdx.y * BM;
    if (bm >= M) return;
    const int bn = blockIdx.x * BN;
    const int t = threadIdx.x;
    const int lr = t >> 1;
    int rr = bm + lr;
    if (rr >= M) rr = M - 1;                 // clamp; extra rows never stored
    const int tokrow = g_gather[e * CAP + rr];
    const float* aptr = X + (size_t)tokrow * HIDD;
    const float* bptr = W + (size_t)e * INTER * HIDD + (size_t)(bn + lr) * HIDD;
    float acc[8][8];
#pragma unroll
    for (int i = 0; i < 8; i++)
#pragma unroll
        for (int j = 0; j < 8; j++) acc[i][j] = 0.f;
    gemm_core(aptr, bptr, true, true, HIDD, acc);
    float* C = Out + (size_t)e * CAP * INTER;
    const int tx = t & 15, ty = t >> 4;
#pragma unroll
    for (int i = 0; i < 8; i++) {
        int r = bm + ty + 16 * i;
        if (r >= M) continue;
#pragma unroll
        for (int j = 0; j < 8; j++) {
            int c = bn + tx + 16 * j;
            C[(size_t)r * INTER + c] = acc[i][j];
        }
    }
}

// down: yb[e, m, :HIDD] = act[e, m, :] @ Wd[e]^T
__global__ void moe_gemm_d(const float* __restrict__ Wd) {
    const int e = blockIdx.z;
    int M = g_cnt[e];
    const int bm = blockIdx.y * BM;
    if (bm >= M) return;
    const int bn = blockIdx.x * BN;
    const int t = threadIdx.x;
    const int lr = t >> 1;
    const float* aptr = g_hg + ((size_t)e * CAP + (bm + lr)) * INTER; // in-bounds; garbage rows unused
    const float* bptr = Wd + (size_t)e * HIDD * INTER + (size_t)(bn + lr) * INTER;
    float acc[8][8];
#pragma unroll
    for (int i = 0; i < 8; i++)
#pragma unroll
        for (int j = 0; j < 8; j++) acc[i][j] = 0.f;
    gemm_core(aptr, bptr, true, true, INTER, acc);
    float* C = g_yb + (size_t)e * CAP * HIDD;
    const int tx = t & 15, ty = t >> 4;
#pragma unroll
    for (int i = 0; i < 8; i++) {
        int r = bm + ty + 16 * i;
        if (r >= M) continue;
#pragma unroll
        for (int j = 0; j < 8; j++) {
            int c = bn + tx + 16 * j;
            C[(size_t)r * HIDD + c] = acc[i][j];
        }
    }
}

// ---------------- flash attention (fp32, causal, 64q x 64k tiles) ----------------
#define FQ 64
#define FK 64
#define QSTR 132
#define SSTR 65

__global__ void flash_k() {
    extern __shared__ float sm[];
    float* Qs = sm;                       // FQ*QSTR
    float* Ks = Qs + FQ * QSTR;
    float* Vs = Ks + FK * QSTR;
    float* Sc = Vs + FK * QSTR;           // FQ*SSTR
    float* alpha_s = Sc + FQ * SSTR;      // FQ
    float* l_s = alpha_s + FQ;            // FQ

    const int qt = blockIdx.x, head = blockIdx.y, b = blockIdx.z;
    const int t = threadIdx.x;            // 128 threads
    const float scale = 0.08838834764831845f; // 1/sqrt(128)
    const size_t headoff = (size_t)head * HD;
    const size_t brow = (size_t)b * SEQ;

    for (int i = t; i < FQ * 32; i += 128) {
        int r = i >> 5, c4 = (i & 31) * 4;
        *(float4*)(Qs + r * QSTR + c4) =
            *(const float4*)(g_q + (brow + qt * FQ + r) * HIDD + headoff + c4);
    }

    float m_i = -INFINITY, l_i = 0.f;     // live in threads t<64
    float outA[64];
#pragma unroll
    for (int i = 0; i < 64; i++) outA[i] = 0.f;
    const int pr = t & 63;                // PV row
    const int ph = t >> 6;                // d-half

    for (int kt = 0; kt <= qt; kt++) {
        for (int i = t; i < FK * 32; i += 128) {
            int r = i >> 5, c4 = (i & 31) * 4;
            size_t g = (brow + kt * FK + r) * HIDD + headoff + c4;
            *(float4*)(Ks + r * QSTR + c4) = *(const float4*)(g_k + g);
            *(float4*)(Vs + r * QSTR + c4) = *(const float4*)(g_v + g);
        }
        __syncthreads();
        // --- scores: S = scale * Q K^T ---
        {
            const int r0 = t & 15, c0 = (t >> 4) * 8;
            float acc[4][8];
#pragma unroll
            for (int i = 0; i < 4; i++)
#pragma unroll
                for (int j = 0; j < 8; j++) acc[i][j] = 0.f;
#pragma unroll 8
            for (int d4 = 0; d4 < HD; d4 += 4) {
                float4 q[4], kx[8];
#pragma unroll
                for (int i = 0; i < 4; i++) q[i] = *(float4*)(Qs + (r0 + 16 * i) * QSTR + d4);
#pragma unroll
                for (int j = 0; j < 8; j++) kx[j] = *(float4*)(Ks + (c0 + j) * QSTR + d4);
#pragma unroll
                for (int i = 0; i < 4; i++)
#pragma unroll
                    for (int j = 0; j < 8; j++)
                        acc[i][j] += q[i].x * kx[j].x + q[i].y * kx[j].y +
                                     q[i].z * kx[j].z + q[i].w * kx[j].w;
            }
#pragma unroll
            for (int i = 0; i < 4; i++)
#pragma unroll
                for (int j = 0; j < 8; j++)
                    Sc[(r0 + 16 * i) * SSTR + c0 + j] = acc[i][j] * scale;
        }
        __syncthreads();
        // --- online softmax (one thread per query row) ---
        if (t < FQ) {
            const int r = t;
            const bool diag = (kt == qt);
            float mx = m_i;
            for (int j = 0; j < FK; j++) {
                float s = Sc[r * SSTR + j];
                if (diag && j > r) s = -INFINITY;
                if (s > mx) mx = s;
            }
            float a = expf(m_i - mx);
            float sum = 0.f;
            for (int j = 0; j < FK; j++) {
                float s = Sc[r * SSTR + j];
                float p = (diag && j > r) ? 0.f : expf(s - mx);
                Sc[r * SSTR + j] = p;
                sum += p;
            }
            l_i = l_i * a + sum;
            m_i = mx;
            alpha_s[r] = a;
        }
        __syncthreads();
        // --- PV accumulate ---
        {
            float a = alpha_s[pr];
#pragma unroll
            for (int i = 0; i < 64; i++) outA[i] *= a;
            for (int j = 0; j < FK; j++) {
                float p = Sc[pr * SSTR + j];
                const float4* vr = (const float4*)(Vs + j * QSTR + ph * 64);
#pragma unroll
                for (int i4 = 0; i4 < 16; i4++) {
                    float4 v = vr[i4];
                    outA[i4 * 4 + 0] += p * v.x;
                    outA[i4 * 4 + 1] += p * v.y;
                    outA[i4 * 4 + 2] += p * v.z;
                    outA[i4 * 4 + 3] += p * v.w;
                }
            }
        }
        __syncthreads();
    }
    if (t < FQ) l_s[t] = l_i;
    __syncthreads();
    float inv = 1.f / l_s[pr];
    size_t orow = (brow + qt * FQ + pr) * HIDD + headoff + ph * 64;
#pragma unroll
    for (int i4 = 0; i4 < 16; i4++) {
        float4 o;
        o.x = outA[i4 * 4 + 0] * inv; o.y = outA[i4 * 4 + 1] * inv;
        o.z = outA[i4 * 4 + 2] * inv; o.w = outA[i4 * 4 + 3] * inv;
        *(float4*)(g_att + orow + i4 * 4) = o;
    }
}

// ---------------- router ----------------
__global__ void zero_cnt_k() { if (threadIdx.x < NE) g_cnt[threadIdx.x] = 0; }

__global__ void router_k(const float* __restrict__ xn, const float* __restrict__ Wr) {
    const int tok = blockIdx.x;
    __shared__ float xs[HIDD];
    __shared__ float lg[NE];
    for (int i = threadIdx.x * 4; i < HIDD; i += blockDim.x * 4)
        *(float4*)(xs + i) = *(const float4*)(xn + (size_t)tok * HIDD + i);
    __syncthreads();
    const int w = threadIdx.x >> 5, lane = threadIdx.x & 31;  // 8 warps = 8 experts
    const float* wr = Wr + (size_t)w * HIDD;
    float s = 0.f;
    for (int i = lane * 4; i < HIDD; i += 128) {
        float4 a = *(const float4*)(xs + i);
        float4 bb = *(const float4*)(wr + i);
        s += a.x * bb.x + a.y * bb.y + a.z * bb.z + a.w * bb.w;
    }
    for (int o = 16; o > 0; o >>= 1) s += __shfl_xor_sync(0xffffffffu, s, o);
    if (lane == 0) lg[w] = s;
    __syncthreads();
    if (threadIdx.x == 0) {
        float b1 = -INFINITY; int i1 = 0;
        for (int e = 0; e < NE; e++) if (lg[e] > b1) { b1 = lg[e]; i1 = e; }
        float b2 = -INFINITY; int i2 = (i1 == 0) ? 1 : 0;
        for (int e = 0; e < NE; e++) if (e != i1 && lg[e] > b2) { b2 = lg[e]; i2 = e; }
        float eo = expf(b2 - b1);
        float w1 = 1.f / (1.f + eo);
        float w2 = eo / (1.f + eo);
        int p1 = atomicAdd(&g_cnt[i1], 1);
        int p2 = atomicAdd(&g_cnt[i2], 1);
        g_gather[i1 * CAP + p1] = tok;
        g_gather[i2 * CAP + p2] = tok;
        g_slots[tok] = make_int2(i1 * CAP + p1, i2 * CAP + p2);
        g_wts[tok] = make_float2(w1, w2);
    }
}

// ---------------- SwiGLU elementwise: act = silu(hg)*hu -> hg ----------------
__global__ void silu_mul_k() {
    const int e = blockIdx.y;
    const int m = blockIdx.x;
    if (m >= g_cnt[e]) return;
    const size_t base = ((size_t)e * CAP + m) * INTER;
    for (int i = threadIdx.x * 4; i < INTER; i += blockDim.x * 4) {
        float4 g = *(float4*)(g_hg + base + i);
        float4 u = *(float4*)(g_hu + base + i);
        g.x = g.x / (1.f + expf(-g.x)) * u.x;
        g.y = g.y / (1.f + expf(-g.y)) * u.y;
        g.z = g.z / (1.f + expf(-g.z)) * u.z;
        g.w = g.w / (1.f + expf(-g.w)) * u.w;
        *(float4*)(g_hg + base + i) = g;
    }
}

// ---------------- final combine: out = x2 + w0*y0 + w1*y1 ----------------
__global__ void combine_k(const float* __restrict__ x2, float* __restrict__ out) {
    const int tok = blockIdx.x;
    const int2 sl = g_slots[tok];
    const float2 w = g_wts[tok];
    const float* y1 = g_yb + (size_t)sl.x * HIDD;
    const float* y2 = g_yb + (size_t)sl.y * HIDD;
    for (int i = threadIdx.x * 4; i < HIDD; i += blockDim.x * 4) {
        float4 a = *(const float4*)(x2 + (size_t)tok * HIDD + i);
        float4 b = *(const float4*)(y1 + i);
        float4 c = *(const float4*)(y2 + i);
        float4 o;
        o.x = a.x + w.x * b.x + w.y * c.x;
        o.y = a.y + w.x * b.y + w.y * c.y;
        o.z = a.z + w.x * b.z + w.y * c.z;
        o.w = a.w + w.x * b.w + w.y * c.w;
        *(float4*)(out + (size_t)tok * HIDD + i) = o;
    }
}

// ---------------- launch ----------------
extern "C" void kernel_launch(void* const* d_in, const int* in_sizes, int n_in,
                              void* d_out, int out_size) {
    (void)in_sizes; (void)n_in; (void)out_size;
    const float* x    = (const float*)d_in[0];
    const float* Wq   = (const float*)d_in[1];
    const float* Wk   = (const float*)d_in[2];
    const float* Wv   = (const float*)d_in[3];
    const float* Wo   = (const float*)d_in[4];
    const float* wln1 = (const float*)d_in[5];
    const float* wln2 = (const float*)d_in[6];
    const float* Wr   = (const float*)d_in[7];
    const float* Wg   = (const float*)d_in[8];
    const float* Wu   = (const float*)d_in[9];
    const float* Wd   = (const float*)d_in[10];
    float* out = (float*)d_out;

    void* p;
    float *xn1, *q, *k, *v, *att, *x2, *xn2, *hg, *hu;
    cudaGetSymbolAddress(&p, g_xn1); xn1 = (float*)p;
    cudaGetSymbolAddress(&p, g_q);   q   = (float*)p;
    cudaGetSymbolAddress(&p, g_k);   k   = (float*)p;
    cudaGetSymbolAddress(&p, g_v);   v   = (float*)p;
    cudaGetSymbolAddress(&p, g_att); att = (float*)p;
    cudaGetSymbolAddress(&p, g_x2);  x2  = (float*)p;
    cudaGetSymbolAddress(&p, g_xn2); xn2 = (float*)p;
    cudaGetSymbolAddress(&p, g_hg);  hg  = (float*)p;
    cudaGetSymbolAddress(&p, g_hu);  hu  = (float*)p;

    const int flash_smem = (3 * FQ * QSTR + FQ * SSTR + 2 * FQ) * (int)sizeof(float);
    cudaFuncSetAttribute(flash_k, cudaFuncAttributeMaxDynamicSharedMemorySize, flash_smem);

    // 1) ln1
    rmsnorm_k<<<T_TOK, 256>>>(x, wln1, xn1);
    // 2) QKV projections
    dim3 g1(HIDD / BN, T_TOK / BM);
    sgemm_tn<<<g1, 256>>>(xn1, Wq, nullptr, q, T_TOK, HIDD, HIDD);
    sgemm_tn<<<g1, 256>>>(xn1, Wk, nullptr, k, T_TOK, HIDD, HIDD);
    sgemm_tn<<<g1, 256>>>(xn1, Wv, nullptr, v, T_TOK, HIDD, HIDD);
    // 3) causal flash attention
    flash_k<<<dim3(SEQ / FQ, NH, NB), 128, flash_smem>>>();
    // 4) O projection + residual
    sgemm_tn<<<g1, 256>>>(att, Wo, x, x2, T_TOK, HIDD, HIDD);
    // 5) ln2
    rmsnorm_k<<<T_TOK, 256>>>(x2, wln2, xn2);
    // 6) routing (top-2 of 8)
    zero_cnt_k<<<1, 32>>>();
    router_k<<<T_TOK, 256>>>(xn2, Wr);
    // 7) MoE expert GEMMs (only chosen tokens per expert)
    dim3 gg(INTER / BN, CAP / BM, NE);
    moe_gemm_gu<<<gg, 256>>>(xn2, Wg, hg);
    moe_gemm_gu<<<gg, 256>>>(xn2, Wu, hu);
    silu_mul_k<<<dim3(CAP, NE), 256>>>();
    dim3 gd(HIDD / BN, CAP / BM, NE);
    moe_gemm_d<<<gd, 256>>>(Wd);
    // 8) combine + final residual
    combine_k<<<T_TOK, 256>>>(x2, out);
}

// round 2
// speedup vs baseline: 1.9701x; 1.9701x over previous
#include <cuda_runtime.h>
#include <math.h>
#include <stdint.h>

#define T_TOK 4096
#define HIDD  2048
#define NH    16
#define HD    128
#define SEQ   2048
#define NB    2
#define NE    8
#define INTER 4096
#define CAP   4096
#define EPS   1e-5f

// ---------------- scratch (__device__ globals: allocation-free) ----------------
__device__ float g_xn1[(size_t)T_TOK * HIDD];
__device__ float g_q  [(size_t)T_TOK * HIDD];
__device__ float g_k  [(size_t)T_TOK * HIDD];
__device__ float g_v  [(size_t)T_TOK * HIDD];
__device__ float g_att[(size_t)T_TOK * HIDD];
__device__ float g_x2 [(size_t)T_TOK * HIDD];
__device__ float g_xn2[(size_t)T_TOK * HIDD];
__device__ float g_hg [(size_t)NE * CAP * INTER];
__device__ float g_hu [(size_t)NE * CAP * INTER];
__device__ float g_yb [(size_t)NE * CAP * HIDD];
__device__ int    g_cnt[NE];
__device__ int    g_gather[NE * CAP];
__device__ int2   g_slots[T_TOK];
__device__ float2 g_wts[T_TOK];

// ---------------- small helpers ----------------
__device__ __forceinline__ uint32_t f2tf32(float x) {
    uint32_t r;
    asm("cvt.rna.tf32.f32 %0, %1;" : "=r"(r) : "f"(x));
    return r;
}

__device__ __forceinline__ void mma8(float* c, const uint32_t* a, const uint32_t* b) {
    asm volatile(
        "mma.sync.aligned.m16n8k8.row.col.f32.tf32.tf32.f32 "
        "{%0,%1,%2,%3}, {%4,%5,%6,%7}, {%8,%9}, {%0,%1,%2,%3};"
        : "+f"(c[0]), "+f"(c[1]), "+f"(c[2]), "+f"(c[3])
        : "r"(a[0]), "r"(a[1]), "r"(a[2]), "r"(a[3]), "r"(b[0]), "r"(b[1]));
}

__device__ __forceinline__ void cp_async16(void* smem, const void* gmem) {
    uint32_t s = (uint32_t)__cvta_generic_to_shared(smem);
    asm volatile("cp.async.cg.shared.global [%0], [%1], 16;\n" :: "r"(s), "l"(gmem));
}
__device__ __forceinline__ void cp_commit() { asm volatile("cp.async.commit_group;\n"); }
__device__ __forceinline__ void cp_wait0()  { asm volatile("cp.async.wait_group 0;\n"); }

// ---------------- tf32 tensor-core GEMM: C[M,N] = A[M,K] @ B[N,K]^T ----------------
// SPLIT: hi/lo tf32 3-pass for ~fp32 accuracy.  MOE: blockIdx.z = expert, M = g_cnt[e].
// GATHER: A rows indirected through g_gather.
#define TBM 128
#define TBN 128
#define TBK 16
#define SPAD 20

template <bool SPLIT, bool MOE, bool GATHER>
__global__ __launch_bounds__(256, 1)
void mma_gemm(const float* __restrict__ A, const float* __restrict__ B,
              const float* __restrict__ resid, float* __restrict__ C,
              int M, int N, int K,
              size_t aes, size_t bes, size_t ces) {
    __shared__ float As[2][TBM][SPAD];
    __shared__ float Bs[2][TBN][SPAD];
    __shared__ int rows_s[TBM];

    const int t = threadIdx.x;
    const int bm = blockIdx.y * TBM, bn = blockIdx.x * TBN;

    if (MOE) {
        int e = blockIdx.z;
        M = g_cnt[e];
        if (bm >= M) return;
        if (!GATHER) A += (size_t)e * aes;
        B += (size_t)e * bes;
        C += (size_t)e * ces;
        if (GATHER && t < TBM) {
            int r = bm + t;
            if (r >= M) r = M - 1;
            rows_s[t] = g_gather[e * CAP + r];
        }
    }
    __syncthreads();

    const int lane = t & 31, wid = t >> 5;
    const int ty = lane >> 2, tx = lane & 3;
    const int rb = (wid >> 2) * 64;   // warp row base within tile
    const int cb = (wid & 3) * 32;    // warp col base within tile

    // per-thread global load coords: 2 float4 per matrix per k-tile
    const int lrow0 = t >> 2, lc0 = (t & 3) * 4;
    const int lrow1 = (t + 256) >> 2, lc1 = ((t + 256) & 3) * 4;

    const float* arow0 = GATHER ? A + (size_t)rows_s[lrow0] * K
                                : A + (size_t)(bm + lrow0) * K;
    const float* arow1 = GATHER ? A + (size_t)rows_s[lrow1] * K
                                : A + (size_t)(bm + lrow1) * K;
    const float* brow0 = B + (size_t)(bn + lrow0) * K;
    const float* brow1 = B + (size_t)(bn + lrow1) * K;

    float acc[4][4][4];
#pragma unroll
    for (int i = 0; i < 4; i++)
#pragma unroll
        for (int j = 0; j < 4; j++)
#pragma unroll
            for (int f = 0; f < 4; f++) acc[i][j][f] = 0.f;

    auto issue = [&](int kt, int buf) {
        int k0 = kt * TBK;
        cp_async16(&As[buf][lrow0][lc0], arow0 + k0 + lc0);
        cp_async16(&As[buf][lrow1][lc1], arow1 + k0 + lc1);
        cp_async16(&Bs[buf][lrow0][lc0], brow0 + k0 + lc0);
        cp_async16(&Bs[buf][lrow1][lc1], brow1 + k0 + lc1);
        cp_commit();
    };

    auto compute = [&](int buf) {
#pragma unroll
        for (int ks = 0; ks < 2; ks++) {
            const int kb = ks * 8;
            uint32_t ahi[4][4], bhi[4][2];
            uint32_t alo[4][4], blo[4][2];
#pragma unroll
            for (int mt = 0; mt < 4; mt++) {
                float a0 = As[buf][rb + mt * 16 + ty][kb + tx];
                float a1 = As[buf][rb + mt * 16 + ty + 8][kb + tx];
                float a2 = As[buf][rb + mt * 16 + ty][kb + tx + 4];
                float a3 = As[buf][rb + mt * 16 + ty + 8][kb + tx + 4];
                ahi[mt][0] = f2tf32(a0); ahi[mt][1] = f2tf32(a1);
                ahi[mt][2] = f2tf32(a2); ahi[mt][3] = f2tf32(a3);
                if (SPLIT) {
                    alo[mt][0] = f2tf32(a0 - __uint_as_float(ahi[mt][0]));
                    alo[mt][1] = f2tf32(a1 - __uint_as_float(ahi[mt][1]));
                    alo[mt][2] = f2tf32(a2 - __uint_as_float(ahi[mt][2]));
                    alo[mt][3] = f2tf32(a3 - __uint_as_float(ahi[mt][3]));
                }
            }
#pragma unroll
            for (int nt = 0; nt < 4; nt++) {
                float b0 = Bs[buf][cb + nt * 8 + ty][kb + tx];
                float b1 = Bs[buf][cb + nt * 8 + ty][kb + tx + 4];
                bhi[nt][0] = f2tf32(b0); bhi[nt][1] = f2tf32(b1);
                if (SPLIT) {
                    blo[nt][0] = f2tf32(b0 - __uint_as_float(bhi[nt][0]));
                    blo[nt][1] = f2tf32(b1 - __uint_as_float(bhi[nt][1]));
                }
            }
#pragma unroll
            for (int mt = 0; mt < 4; mt++)
#pragma unroll
                for (int nt = 0; nt < 4; nt++) {
                    mma8(acc[mt][nt], ahi[mt], bhi[nt]);
                    if (SPLIT) {
                        mma8(acc[mt][nt], ahi[mt], blo[nt]);
                        mma8(acc[mt][nt], alo[mt], bhi[nt]);
                    }
                }
        }
    };

    const int nk = K / TBK;
    issue(0, 0);
    cp_wait0();
    __syncthreads();
    for (int kt = 0; kt < nk; kt++) {
        const int cur = kt & 1;
        if (kt + 1 < nk) issue(kt + 1, cur ^ 1);
        compute(cur);
        if (kt + 1 < nk) cp_wait0();
        __syncthreads();
    }

    // epilogue
#pragma unroll
    for (int mt = 0; mt < 4; mt++) {
#pragma unroll
        for (int nt = 0; nt < 4; nt++) {
            int r0 = bm + rb + mt * 16 + ty;
            int c0 = bn + cb + nt * 8 + 2 * tx;
            if (!MOE || r0 < M) {
                float2 v = make_float2(acc[mt][nt][0], acc[mt][nt][1]);
                if (resid) {
                    v.x += resid[(size_t)r0 * N + c0];
                    v.y += resid[(size_t)r0 * N + c0 + 1];
                }
                *(float2*)(C + (size_t)r0 * N + c0) = v;
            }
            int r1 = r0 + 8;
            if (!MOE || r1 < M) {
                float2 v = make_float2(acc[mt][nt][2], acc[mt][nt][3]);
                if (resid) {
                    v.x += resid[(size_t)r1 * N + c0];
                    v.y += resid[(size_t)r1 * N + c0 + 1];
                }
                *(float2*)(C + (size_t)r1 * N + c0) = v;
            }
        }
    }
}

// ---------------- RMSNorm ----------------
__global__ void rmsnorm_k(const float* __restrict__ x, const float* __restrict__ w,
                          float* __restrict__ y) {
    int tok = blockIdx.x;
    const float* xr = x + (size_t)tok * HIDD;
    float s = 0.f;
    for (int i = threadIdx.x * 4; i < HIDD; i += blockDim.x * 4) {
        float4 v = *(const float4*)(xr + i);
        s += v.x * v.x + v.y * v.y + v.z * v.z + v.w * v.w;
    }
    __shared__ float red[32];
    for (int o = 16; o > 0; o >>= 1) s += __shfl_xor_sync(0xffffffffu, s, o);
    if ((threadIdx.x & 31) == 0) red[threadIdx.x >> 5] = s;
    __syncthreads();
    if (threadIdx.x < 32) {
        float v = (threadIdx.x < (blockDim.x >> 5)) ? red[threadIdx.x] : 0.f;
        for (int o = 4; o > 0; o >>= 1) v += __shfl_xor_sync(0xffffffffu, v, o);
        if (threadIdx.x == 0) red[0] = rsqrtf(v / (float)HIDD + EPS);
    }
    __syncthreads();
    float sc = red[0];
    float* yr = y + (size_t)tok * HIDD;
    for (int i = threadIdx.x * 4; i < HIDD; i += blockDim.x * 4) {
        float4 v = *(const float4*)(xr + i);
        float4 wv = *(const float4*)(w + i);
        float4 o;
        o.x = v.x * sc * wv.x; o.y = v.y * sc * wv.y;
        o.z = v.z * sc * wv.z; o.w = v.w * sc * wv.w;
        *(float4*)(yr + i) = o;
    }
}

// ---------------- flash attention (fp32, causal, 64q x 64k tiles) ----------------
#define FQ 64
#define FK 64
#define QSTR 132
#define SSTR 65

__global__ void flash_k() {
    extern __shared__ float sm[];
    float* Qs = sm;
    float* Ks = Qs + FQ * QSTR;
    float* Vs = Ks + FK * QSTR;
    float* Sc = Vs + FK * QSTR;
    float* alpha_s = Sc + FQ * SSTR;
    float* l_s = alpha_s + FQ;

    const int qt = blockIdx.x, head = blockIdx.y, b = blockIdx.z;
    const int t = threadIdx.x;
    const float scale = 0.08838834764831845f;
    const size_t headoff = (size_t)head * HD;
    const size_t brow = (size_t)b * SEQ;

    for (int i = t; i < FQ * 32; i += 128) {
        int r = i >> 5, c4 = (i & 31) * 4;
        *(float4*)(Qs + r * QSTR + c4) =
            *(const float4*)(g_q + (brow + qt * FQ + r) * HIDD + headoff + c4);
    }

    float m_i = -INFINITY, l_i = 0.f;
    float outA[64];
#pragma unroll
    for (int i = 0; i < 64; i++) outA[i] = 0.f;
    const int pr = t & 63;
    const int ph = t >> 6;

    for (int kt = 0; kt <= qt; kt++) {
        for (int i = t; i < FK * 32; i += 128) {
            int r = i >> 5, c4 = (i & 31) * 4;
            size_t g = (brow + kt * FK + r) * HIDD + headoff + c4;
            *(float4*)(Ks + r * QSTR + c4) = *(const float4*)(g_k + g);
            *(float4*)(Vs + r * QSTR + c4) = *(const float4*)(g_v + g);
        }
        __syncthreads();
        {
            const int r0 = t & 15, c0 = (t >> 4) * 8;
            float acc[4][8];
#pragma unroll
            for (int i = 0; i < 4; i++)
#pragma unroll
                for (int j = 0; j < 8; j++) acc[i][j] = 0.f;
#pragma unroll 8
            for (int d4 = 0; d4 < HD; d4 += 4) {
                float4 q[4], kx[8];
#pragma unroll
                for (int i = 0; i < 4; i++) q[i] = *(float4*)(Qs + (r0 + 16 * i) * QSTR + d4);
#pragma unroll
                for (int j = 0; j < 8; j++) kx[j] = *(float4*)(Ks + (c0 + j) * QSTR + d4);
#pragma unroll
                for (int i = 0; i < 4; i++)
#pragma unroll
                    for (int j = 0; j < 8; j++)
                        acc[i][j] += q[i].x * kx[j].x + q[i].y * kx[j].y +
                                     q[i].z * kx[j].z + q[i].w * kx[j].w;
            }
#pragma unroll
            for (int i = 0; i < 4; i++)
#pragma unroll
                for (int j = 0; j < 8; j++)
                    Sc[(r0 + 16 * i) * SSTR + c0 + j] = acc[i][j] * scale;
        }
        __syncthreads();
        if (t < FQ) {
            const int r = t;
            const bool diag = (kt == qt);
            float mx = m_i;
            for (int j = 0; j < FK; j++) {
                float s = Sc[r * SSTR + j];
                if (diag && j > r) s = -INFINITY;
                if (s > mx) mx = s;
            }
            float a = expf(m_i - mx);
            float sum = 0.f;
            for (int j = 0; j < FK; j++) {
                float s = Sc[r * SSTR + j];
                float p = (diag && j > r) ? 0.f : expf(s - mx);
                Sc[r * SSTR + j] = p;
                sum += p;
            }
            l_i = l_i * a + sum;
            m_i = mx;
            alpha_s[r] = a;
        }
        __syncthreads();
        {
            float a = alpha_s[pr];
#pragma unroll
            for (int i = 0; i < 64; i++) outA[i] *= a;
            for (int j = 0; j < FK; j++) {
                float p = Sc[pr * SSTR + j];
                const float4* vr = (const float4*)(Vs + j * QSTR + ph * 64);
#pragma unroll
                for (int i4 = 0; i4 < 16; i4++) {
                    float4 v = vr[i4];
                    outA[i4 * 4 + 0] += p * v.x;
                    outA[i4 * 4 + 1] += p * v.y;
                    outA[i4 * 4 + 2] += p * v.z;
                    outA[i4 * 4 + 3] += p * v.w;
                }
            }
        }
        __syncthreads();
    }
    if (t < FQ) l_s[t] = l_i;
    __syncthreads();
    float inv = 1.f / l_s[pr];
    size_t orow = (brow + qt * FQ + pr) * HIDD + headoff + ph * 64;
#pragma unroll
    for (int i4 = 0; i4 < 16; i4++) {
        float4 o;
        o.x = outA[i4 * 4 + 0] * inv; o.y = outA[i4 * 4 + 1] * inv;
        o.z = outA[i4 * 4 + 2] * inv; o.w = outA[i4 * 4 + 3] * inv;
        *(float4*)(g_att + orow + i4 * 4) = o;
    }
}

// ---------------- router ----------------
__global__ void zero_cnt_k() { if (threadIdx.x < NE) g_cnt[threadIdx.x] = 0; }

__global__ void router_k(const float* __restrict__ xn, const float* __restrict__ Wr) {
    const int tok = blockIdx.x;
    __shared__ float xs[HIDD];
    __shared__ float lg[NE];
    for (int i = threadIdx.x * 4; i < HIDD; i += blockDim.x * 4)
        *(float4*)(xs + i) = *(const float4*)(xn + (size_t)tok * HIDD + i);
    __syncthreads();
    const int w = threadIdx.x >> 5, lane = threadIdx.x & 31;
    const float* wr = Wr + (size_t)w * HIDD;
    float s = 0.f;
    for (int i = lane * 4; i < HIDD; i += 128) {
        float4 a = *(const float4*)(xs + i);
        float4 bb = *(const float4*)(wr + i);
        s += a.x * bb.x + a.y * bb.y + a.z * bb.z + a.w * bb.w;
    }
    for (int o = 16; o > 0; o >>= 1) s += __shfl_xor_sync(0xffffffffu, s, o);
    if (lane == 0) lg[w] = s;
    __syncthreads();
    if (threadIdx.x == 0) {
        float b1 = -INFINITY; int i1 = 0;
        for (int e = 0; e < NE; e++) if (lg[e] > b1) { b1 = lg[e]; i1 = e; }
        float b2 = -INFINITY; int i2 = (i1 == 0) ? 1 : 0;
        for (int e = 0; e < NE; e++) if (e != i1 && lg[e] > b2) { b2 = lg[e]; i2 = e; }
        float eo = expf(b2 - b1);
        float w1 = 1.f / (1.f + eo);
        float w2 = eo / (1.f + eo);
        int p1 = atomicAdd(&g_cnt[i1], 1);
        int p2 = atomicAdd(&g_cnt[i2], 1);
        g_gather[i1 * CAP + p1] = tok;
        g_gather[i2 * CAP + p2] = tok;
        g_slots[tok] = make_int2(i1 * CAP + p1, i2 * CAP + p2);
        g_wts[tok] = make_float2(w1, w2);
    }
}

// ---------------- SwiGLU elementwise ----------------
__global__ void silu_mul_k() {
    const int e = blockIdx.y;
    const int m = blockIdx.x;
    if (m >= g_cnt[e]) return;
    const size_t base = ((size_t)e * CAP + m) * INTER;
    for (int i = threadIdx.x * 4; i < INTER; i += blockDim.x * 4) {
        float4 g = *(float4*)(g_hg + base + i);
        float4 u = *(float4*)(g_hu + base + i);
        g.x = g.x / (1.f + expf(-g.x)) * u.x;
        g.y = g.y / (1.f + expf(-g.y)) * u.y;
        g.z = g.z / (1.f + expf(-g.z)) * u.z;
        g.w = g.w / (1.f + expf(-g.w)) * u.w;
        *(float4*)(g_hg + base + i) = g;
    }
}

// ---------------- final combine ----------------
__global__ void combine_k(const float* __restrict__ x2, float* __restrict__ out) {
    const int tok = blockIdx.x;
    const int2 sl = g_slots[tok];
    const float2 w = g_wts[tok];
    const float* y1 = g_yb + (size_t)sl.x * HIDD;
    const float* y2 = g_yb + (size_t)sl.y * HIDD;
    for (int i = threadIdx.x * 4; i < HIDD; i += blockDim.x * 4) {
        float4 a = *(const float4*)(x2 + (size_t)tok * HIDD + i);
        float4 b = *(const float4*)(y1 + i);
        float4 c = *(const float4*)(y2 + i);
        float4 o;
        o.x = a.x + w.x * b.x + w.y * c.x;
        o.y = a.y + w.x * b.y + w.y * c.y;
        o.z = a.z + w.x * b.z + w.y * c.z;
        o.w = a.w + w.x * b.w + w.y * c.w;
        *(float4*)(out + (size_t)tok * HIDD + i) = o;
    }
}

// ---------------- launch ----------------
extern "C" void kernel_launch(void* const* d_in, const int* in_sizes, int n_in,
                              void* d_out, int out_size) {
    (void)in_sizes; (void)n_in; (void)out_size;
    const float* x    = (const float*)d_in[0];
    const float* Wq   = (const float*)d_in[1];
    const float* Wk   = (const float*)d_in[2];
    const float* Wv   = (const float*)d_in[3];
    const float* Wo   = (const float*)d_in[4];
    const float* wln1 = (const float*)d_in[5];
    const float* wln2 = (const float*)d_in[6];
    const float* Wr   = (const float*)d_in[7];
    const float* Wg   = (const float*)d_in[8];
    const float* Wu   = (const float*)d_in[9];
    const float* Wd   = (const float*)d_in[10];
    float* out = (float*)d_out;

    void* p;
    float *xn1, *q, *k, *v, *att, *x2, *xn2, *hg, *hu, *yb;
    cudaGetSymbolAddress(&p, g_xn1); xn1 = (float*)p;
    cudaGetSymbolAddress(&p, g_q);   q   = (float*)p;
    cudaGetSymbolAddress(&p, g_k);   k   = (float*)p;
    cudaGetSymbolAddress(&p, g_v);   v   = (float*)p;
    cudaGetSymbolAddress(&p, g_att); att = (float*)p;
    cudaGetSymbolAddress(&p, g_x2);  x2  = (float*)p;
    cudaGetSymbolAddress(&p, g_xn2); xn2 = (float*)p;
    cudaGetSymbolAddress(&p, g_hg);  hg  = (float*)p;
    cudaGetSymbolAddress(&p, g_hu);  hu  = (float*)p;
    cudaGetSymbolAddress(&p, g_yb);  yb  = (float*)p;

    const int flash_smem = (3 * FQ * QSTR + FQ * SSTR + 2 * FQ) * (int)sizeof(float);
    cudaFuncSetAttribute(flash_k, cudaFuncAttributeMaxDynamicSharedMemorySize, flash_smem);

    // 1) ln1
    rmsnorm_k<<<T_TOK, 256>>>(x, wln1, xn1);
    // 2) QKV projections — split-tf32 (full precision, feeds router path)
    dim3 g1(HIDD / TBN, T_TOK / TBM);
    mma_gemm<true, false, false><<<g1, 256>>>(xn1, Wq, nullptr, q, T_TOK, HIDD, HIDD, 0, 0, 0);
    mma_gemm<true, false, false><<<g1, 256>>>(xn1, Wk, nullptr, k, T_TOK, HIDD, HIDD, 0, 0, 0);
    mma_gemm<true, false, false><<<g1, 256>>>(xn1, Wv, nullptr, v, T_TOK, HIDD, HIDD, 0, 0, 0);
    // 3) causal flash attention (fp32)
    flash_k<<<dim3(SEQ / FQ, NH, NB), 128, flash_smem>>>();
    // 4) O projection + residual — split-tf32
    mma_gemm<true, false, false><<<g1, 256>>>(att, Wo, x, x2, T_TOK, HIDD, HIDD, 0, 0, 0);
    // 5) ln2
    rmsnorm_k<<<T_TOK, 256>>>(x2, wln2, xn2);
    // 6) routing (top-2 of 8), fp32
    zero_cnt_k<<<1, 32>>>();
    router_k<<<T_TOK, 256>>>(xn2, Wr);
    // 7) MoE expert GEMMs — single-pass tf32 (downstream of routing, smooth errors)
    dim3 gg(INTER / TBN, CAP / TBM, NE);
    mma_gemm<false, true, true><<<gg, 256>>>(xn2, Wg, nullptr, hg, 0, INTER, HIDD,
                                             0, (size_t)INTER * HIDD, (size_t)CAP * INTER);
    mma_gemm<false, true, true><<<gg, 256>>>(xn2, Wu, nullptr, hu, 0, INTER, HIDD,
                                             0, (size_t)INTER * HIDD, (size_t)CAP * INTER);
    silu_mul_k<<<dim3(CAP, NE), 256>>>();
    dim3 gd(HIDD / TBN, CAP / TBM, NE);
    mma_gemm<false, true, false><<<gd, 256>>>(hg, Wd, nullptr, yb, 0, HIDD, INTER,
                                              (size_t)CAP * INTER, (size_t)HIDD * INTER,
                                              (size_t)CAP * HIDD);
    // 8) combine + final residual
    combine_k<<<T_TOK, 256>>>(x2, out);
}

// round 7
// speedup vs baseline: 3.5511x; 1.8025x over previous
#include <cuda_runtime.h>
#include <cuda_fp16.h>
#include <math.h>
#include <stdint.h>

#define T_TOK 4096
#define HIDD  2048
#define NH    16
#define HD    128
#define SEQ   2048
#define NB    2
#define NE    8
#define INTER 4096
#define CAP   4096
#define EPS   1e-5f
#define QKVW  6144

// ---------------- scratch ----------------
__device__ __half g_xn1h[(size_t)T_TOK * HIDD];
__device__ __half g_xn1l[(size_t)T_TOK * HIDD];
__device__ __half g_qkvh[(size_t)T_TOK * QKVW];
__device__ __half g_qkvl[(size_t)T_TOK * QKVW];
__device__ __half g_atth[(size_t)T_TOK * HIDD];
__device__ __half g_attl[(size_t)T_TOK * HIDD];
__device__ float  g_x2  [(size_t)T_TOK * HIDD];
__device__ float  g_xn2 [(size_t)T_TOK * HIDD];
__device__ float  g_hg  [(size_t)NE * CAP * INTER];
__device__ float  g_hu  [(size_t)NE * CAP * INTER];
__device__ float  g_yb  [(size_t)NE * CAP * HIDD];
__device__ __half g_wqkvh[(size_t)QKVW * HIDD];
__device__ __half g_wqkvl[(size_t)QKVW * HIDD];
__device__ __half g_woh[(size_t)HIDD * HIDD];
__device__ __half g_wol[(size_t)HIDD * HIDD];
__device__ int    g_cnt[NE];
__device__ int    g_gather[NE * CAP];
__device__ int2   g_slots[T_TOK];
__device__ float2 g_wts[T_TOK];

// ---------------- helpers ----------------
__device__ __forceinline__ uint32_t f2tf32(float x) {
    uint32_t r;
    asm("cvt.rna.tf32.f32 %0, %1;" : "=r"(r) : "f"(x));
    return r;
}
__device__ __forceinline__ void mma8(float* c, const uint32_t* a, const uint32_t* b) {
    asm volatile(
        "mma.sync.aligned.m16n8k8.row.col.f32.tf32.tf32.f32 "
        "{%0,%1,%2,%3}, {%4,%5,%6,%7}, {%8,%9}, {%0,%1,%2,%3};"
        : "+f"(c[0]), "+f"(c[1]), "+f"(c[2]), "+f"(c[3])
        : "r"(a[0]), "r"(a[1]), "r"(a[2]), "r"(a[3]), "r"(b[0]), "r"(b[1]));
}
__device__ __forceinline__ void mma16(float* c, const uint32_t* a, uint32_t b0, uint32_t b1) {
    asm volatile(
        "mma.sync.aligned.m16n8k16.row.col.f32.f16.f16.f32 "
        "{%0,%1,%2,%3}, {%4,%5,%6,%7}, {%8,%9}, {%0,%1,%2,%3};"
        : "+f"(c[0]), "+f"(c[1]), "+f"(c[2]), "+f"(c[3])
        : "r"(a[0]), "r"(a[1]), "r"(a[2]), "r"(a[3]), "r"(b0), "r"(b1));
}
__device__ __forceinline__ void cp_async16(void* smem, const void* gmem) {
    uint32_t s = (uint32_t)__cvta_generic_to_shared(smem);
    asm volatile("cp.async.cg.shared.global [%0], [%1], 16;\n" :: "r"(s), "l"(gmem));
}
__device__ __forceinline__ void cp_commit() { asm volatile("cp.async.commit_group;\n"); }
__device__ __forceinline__ void cp_wait0()  { asm volatile("cp.async.wait_group 0;\n"); }
__device__ __forceinline__ uint32_t ld32s(const __half* p) { return *(const uint32_t*)p; }

__device__ __forceinline__ void split16(float x, __half& h, __half& l) {
    h = __float2half_rn(x);
    l = __float2half_rn(x - __half2float(h));
}

// =========================================================================
// fp16-split GEMM: C[M,N] = (Ah+Al)[M,K] @ (Bh+Bl)[N,K]^T  (3-pass)
// =========================================================================
#define HBM 128
#define HBN 128
#define HBK 32
#define HS  40            // smem row stride in halves
#define HTILE (128 * HS)  // halves per tile per buf

template <bool EPI16>
__global__ __launch_bounds__(256)
void hgemm(const __half* __restrict__ Ah, const __half* __restrict__ Al,
           const __half* __restrict__ Bh, const __half* __restrict__ Bl,
           const float* __restrict__ resid, float* __restrict__ Cf,
           __half* __restrict__ Ch, __half* __restrict__ Cl,
           int M, int N, int K) {
    extern __shared__ __half hsm[];
    // layout: [Ah b0, Ah b1, Al b0, Al b1, Bh b0, Bh b1, Bl b0, Bl b1]
    const int t = threadIdx.x, lane = t & 31, wid = t >> 5;
    const int lq = lane >> 2, lr = lane & 3;
    const int rb = (wid >> 2) * 64, cb = (wid & 3) * 32;
    const int bm = blockIdx.y * HBM, bn = blockIdx.x * HBN;

    float acc[4][4][4];
#pragma unroll
    for (int i = 0; i < 4; i++)
#pragma unroll
        for (int j = 0; j < 4; j++)
#pragma unroll
            for (int f = 0; f < 4; f++) acc[i][j][f] = 0.f;

    // load slots: per tile 512 segs (128 rows x 4 segs of 8 halves), 2 per thread
    const int r0 = t >> 1;                 // slot t:    row t>>2... use slot arithmetic below
    (void)r0;

    auto tptr = [&](int arr, int buf) { return hsm + (size_t)(arr * 2 + buf) * HTILE; };

    auto issue = [&](int c, int buf) {
        const int k0 = c * HBK;
#pragma unroll
        for (int i = 0; i < 2; i++) {
            int slot = t + 256 * i;
            int row = slot >> 2, sg = (slot & 3) * 8;
            size_t goff = (size_t)row * K + k0 + sg;
            cp_async16(tptr(0, buf) + row * HS + sg, Ah + (size_t)bm * K + goff);
            cp_async16(tptr(1, buf) + row * HS + sg, Al + (size_t)bm * K + goff);
            cp_async16(tptr(2, buf) + row * HS + sg, Bh + (size_t)bn * K + goff);
            cp_async16(tptr(3, buf) + row * HS + sg, Bl + (size_t)bn * K + goff);
        }
        cp_commit();
    };

    auto compute = [&](int buf) {
        const __half* tAh = tptr(0, buf);
        const __half* tAl = tptr(1, buf);
        const __half* tBh = tptr(2, buf);
        const __half* tBl = tptr(3, buf);
#pragma unroll
        for (int ks = 0; ks < 2; ks++) {
            const int k0 = ks * 16;
            uint32_t ah[4][4], al[4][4], bh[4][2], bl[4][2];
#pragma unroll
            for (int mt = 0; mt < 4; mt++) {
                const __half* p = tAh + (rb + mt * 16 + lq) * HS + k0 + lr * 2;
                const __half* q = tAl + (rb + mt * 16 + lq) * HS + k0 + lr * 2;
                ah[mt][0] = ld32s(p);          ah[mt][1] = ld32s(p + 8 * HS);
                ah[mt][2] = ld32s(p + 8);      ah[mt][3] = ld32s(p + 8 * HS + 8);
                al[mt][0] = ld32s(q);          al[mt][1] = ld32s(q + 8 * HS);
                al[mt][2] = ld32s(q + 8);      al[mt][3] = ld32s(q + 8 * HS + 8);
            }
#pragma unroll
            for (int nt = 0; nt < 4; nt++) {
                const __half* p = tBh + (cb + nt * 8 + lq) * HS + k0 + lr * 2;
                const __half* q = tBl + (cb + nt * 8 + lq) * HS + k0 + lr * 2;
                bh[nt][0] = ld32s(p); bh[nt][1] = ld32s(p + 8);
                bl[nt][0] = ld32s(q); bl[nt][1] = ld32s(q + 8);
            }
#pragma unroll
            for (int mt = 0; mt < 4; mt++)
#pragma unroll
                for (int nt = 0; nt < 4; nt++) {
                    mma16(acc[mt][nt], ah[mt], bh[nt][0], bh[nt][1]);
                    mma16(acc[mt][nt], ah[mt], bl[nt][0], bl[nt][1]);
                    mma16(acc[mt][nt], al[mt], bh[nt][0], bh[nt][1]);
                }
        }
    };

    const int nk = K / HBK;
    issue(0, 0);
    cp_wait0();
    __syncthreads();
    for (int c = 0; c < nk; c++) {
        const int cur = c & 1;
        if (c + 1 < nk) issue(c + 1, cur ^ 1);
        compute(cur);
        if (c + 1 < nk) cp_wait0();
        __syncthreads();
    }

#pragma unroll
    for (int mt = 0; mt < 4; mt++)
#pragma unroll
        for (int nt = 0; nt < 4; nt++) {
            int r0g = bm + rb + mt * 16 + lq;
            int r1g = r0g + 8;
            int c0 = bn + cb + nt * 8 + lr * 2;
            if (EPI16) {
                __half h0, l0, h1, l1;
                split16(acc[mt][nt][0], h0, l0); split16(acc[mt][nt][1], h1, l1);
                *(__half2*)(Ch + (size_t)r0g * N + c0) = __halves2half2(h0, h1);
                *(__half2*)(Cl + (size_t)r0g * N + c0) = __halves2half2(l0, l1);
                split16(acc[mt][nt][2], h0, l0); split16(acc[mt][nt][3], h1, l1);
                *(__half2*)(Ch + (size_t)r1g * N + c0) = __halves2half2(h0, h1);
                *(__half2*)(Cl + (size_t)r1g * N + c0) = __halves2half2(l0, l1);
            } else {
                float2 v0 = make_float2(acc[mt][nt][0], acc[mt][nt][1]);
                float2 v1 = make_float2(acc[mt][nt][2], acc[mt][nt][3]);
                if (resid) {
                    v0.x += resid[(size_t)r0g * N + c0]; v0.y += resid[(size_t)r0g * N + c0 + 1];
                    v1.x += resid[(size_t)r1g * N + c0]; v1.y += resid[(size_t)r1g * N + c0 + 1];
                }
                *(float2*)(Cf + (size_t)r0g * N + c0) = v0;
                *(float2*)(Cf + (size_t)r1g * N + c0) = v1;
            }
        }
}

// =========================================================================
// MoE tf32 GEMM (proven round-2 kernel, MOE-only)
// =========================================================================
#define TBM 128
#define TBN 128
#define TBK 16
#define SPAD 20

template <bool GATHER>
__global__ __launch_bounds__(256, 1)
void moe_gemm(const float* __restrict__ A, const float* __restrict__ B,
              float* __restrict__ C, int N, int K,
              size_t aes, size_t bes, size_t ces) {
    __shared__ float As[2][TBM][SPAD];
    __shared__ float Bs[2][TBN][SPAD];
    __shared__ int rows_s[TBM];

    const int t = threadIdx.x;
    const int bm = blockIdx.y * TBM, bn = blockIdx.x * TBN;

    int e = blockIdx.z;
    int M = g_cnt[e];
    if (bm >= M) return;
    A += (size_t)e * aes;
    B += (size_t)e * bes;
    C += (size_t)e * ces;
    if (GATHER && t < TBM) {
        int r = bm + t;
        if (r >= M) r = M - 1;
        rows_s[t] = g_gather[e * CAP + r];
    }
    __syncthreads();

    const int lane = t & 31, wid = t >> 5;
    const int ty = lane >> 2, tx = lane & 3;
    const int rb = (wid >> 2) * 64;
    const int cb = (wid & 3) * 32;

    const int lrow0 = t >> 2, lc0 = (t & 3) * 4;
    const int lrow1 = (t + 256) >> 2, lc1 = ((t + 256) & 3) * 4;

    const float* arow0 = GATHER ? A + (size_t)rows_s[lrow0] * K
                                : A + (size_t)(bm + lrow0) * K;
    const float* arow1 = GATHER ? A + (size_t)rows_s[lrow1] * K
                                : A + (size_t)(bm + lrow1) * K;
    const float* brow0 = B + (size_t)(bn + lrow0) * K;
    const float* brow1 = B + (size_t)(bn + lrow1) * K;

    float acc[4][4][4];
#pragma unroll
    for (int i = 0; i < 4; i++)
#pragma unroll
        for (int j = 0; j < 4; j++)
#pragma unroll
            for (int f = 0; f < 4; f++) acc[i][j][f] = 0.f;

    auto issue = [&](int kt, int buf) {
        int k0 = kt * TBK;
        cp_async16(&As[buf][lrow0][lc0], arow0 + k0 + lc0);
        cp_async16(&As[buf][lrow1][lc1], arow1 + k0 + lc1);
        cp_async16(&Bs[buf][lrow0][lc0], brow0 + k0 + lc0);
        cp_async16(&Bs[buf][lrow1][lc1], brow1 + k0 + lc1);
        cp_commit();
    };

    auto compute = [&](int buf) {
#pragma unroll
        for (int ks = 0; ks < 2; ks++) {
            const int kb = ks * 8;
            uint32_t ahi[4][4], bhi[4][2];
#pragma unroll
            for (int mt = 0; mt < 4; mt++) {
                ahi[mt][0] = f2tf32(As[buf][rb + mt * 16 + ty][kb + tx]);
                ahi[mt][1] = f2tf32(As[buf][rb + mt * 16 + ty + 8][kb + tx]);
                ahi[mt][2] = f2tf32(As[buf][rb + mt * 16 + ty][kb + tx + 4]);
                ahi[mt][3] = f2tf32(As[buf][rb + mt * 16 + ty + 8][kb + tx + 4]);
            }
#pragma unroll
            for (int nt = 0; nt < 4; nt++) {
                bhi[nt][0] = f2tf32(Bs[buf][cb + nt * 8 + ty][kb + tx]);
                bhi[nt][1] = f2tf32(Bs[buf][cb + nt * 8 + ty][kb + tx + 4]);
            }
#pragma unroll
            for (int mt = 0; mt < 4; mt++)
#pragma unroll
                for (int nt = 0; nt < 4; nt++)
                    mma8(acc[mt][nt], ahi[mt], bhi[nt]);
        }
    };

    const int nk = K / TBK;
    issue(0, 0);
    cp_wait0();
    __syncthreads();
    for (int kt = 0; kt < nk; kt++) {
        const int cur = kt & 1;
        if (kt + 1 < nk) issue(kt + 1, cur ^ 1);
        compute(cur);
        if (kt + 1 < nk) cp_wait0();
        __syncthreads();
    }

#pragma unroll
    for (int mt = 0; mt < 4; mt++)
#pragma unroll
        for (int nt = 0; nt < 4; nt++) {
            int r0 = bm + rb + mt * 16 + ty;
            int c0 = bn + cb + nt * 8 + 2 * tx;
            if (r0 < M)
                *(float2*)(C + (size_t)r0 * N + c0) =
                    make_float2(acc[mt][nt][0], acc[mt][nt][1]);
            if (r0 + 8 < M)
                *(float2*)(C + (size_t)(r0 + 8) * N + c0) =
                    make_float2(acc[mt][nt][2], acc[mt][nt][3]);
        }
}

// =========================================================================
// flash attention: fp16-split mma, causal, 64q x 64k tiles, 4 warps
// =========================================================================
#define QS 136
#define VS 72
#define FLASH_SMEM ((4 * 64 * QS + 2 * 128 * VS) * 2)

__global__ __launch_bounds__(128)
void flash_mma_k() {
    extern __shared__ __half fsm[];
    __half* Qh  = fsm;
    __half* Ql  = Qh + 64 * QS;
    __half* Kh  = Ql + 64 * QS;
    __half* Kl  = Kh + 64 * QS;
    __half* Vth = Kl + 64 * QS;
    __half* Vtl = Vth + 128 * VS;

    const int qt = blockIdx.x, head = blockIdx.y, b = blockIdx.z;
    const int t = threadIdx.x, wid = t >> 5, lane = t & 31;
    const int lq = lane >> 2, lr = lane & 3;
    const int wr = wid * 16;
    const float scale = 0.08838834764831845f;
    const size_t base = (size_t)b * SEQ * QKVW;
    const size_t qoff = (size_t)head * HD;
    const size_t koff = 2048 + qoff, voff = 4096 + qoff;

    // load Q tile
    for (int i = t; i < 64 * 16; i += 128) {
        int r = i >> 4, sg = (i & 15) * 8;
        size_t g = base + (size_t)(qt * 64 + r) * QKVW + qoff + sg;
        *(uint4*)(Qh + r * QS + sg) = *(const uint4*)(g_qkvh + g);
        *(uint4*)(Ql + r * QS + sg) = *(const uint4*)(g_qkvl + g);
    }

    float out[16][4];
#pragma unroll
    for (int i = 0; i < 16; i++)
#pragma unroll
        for (int j = 0; j < 4; j++) out[i][j] = 0.f;
    float m0 = -INFINITY, m1 = -INFINITY, l0 = 0.f, l1 = 0.f;

    for (int kt = 0; kt <= qt; kt++) {
        __syncthreads();
        for (int i = t; i < 64 * 16; i += 128) {
            int r = i >> 4, sg = (i & 15) * 8;
            size_t g = base + (size_t)(kt * 64 + r) * QKVW + koff + sg;
            *(uint4*)(Kh + r * QS + sg) = *(const uint4*)(g_qkvh + g);
            *(uint4*)(Kl + r * QS + sg) = *(const uint4*)(g_qkvl + g);
        }
        for (int i = t; i < 64 * 64; i += 128) {
            int r = i >> 6, dp = i & 63;
            size_t g = base + (size_t)(kt * 64 + r) * QKVW + voff + dp * 2;
            __half2 vh = *(const __half2*)(g_qkvh + g);
            __half2 vl = *(const __half2*)(g_qkvl + g);
            Vth[(2 * dp) * VS + r]     = __low2half(vh);
            Vth[(2 * dp + 1) * VS + r] = __high2half(vh);
            Vtl[(2 * dp) * VS + r]     = __low2half(vl);
            Vtl[(2 * dp + 1) * VS + r] = __high2half(vl);
        }
        __syncthreads();

        // ---- S = Q K^T (fp16 split, 3-pass) ----
        float s[8][4];
#pragma unroll
        for (int i = 0; i < 8; i++)
#pragma unroll
            for (int j = 0; j < 4; j++) s[i][j] = 0.f;

        for (int kc = 0; kc < 8; kc++) {
            uint32_t ah[4], al[4];
            const __half* qp = Qh + (wr + lq) * QS + kc * 16 + lr * 2;
            const __half* ql = Ql + (wr + lq) * QS + kc * 16 + lr * 2;
            ah[0] = ld32s(qp);     ah[1] = ld32s(qp + 8 * QS);
            ah[2] = ld32s(qp + 8); ah[3] = ld32s(qp + 8 * QS + 8);
            al[0] = ld32s(ql);     al[1] = ld32s(ql + 8 * QS);
            al[2] = ld32s(ql + 8); al[3] = ld32s(ql + 8 * QS + 8);
#pragma unroll
            for (int nt = 0; nt < 8; nt++) {
                const __half* kp = Kh + (nt * 8 + lq) * QS + kc * 16 + lr * 2;
                const __half* kl = Kl + (nt * 8 + lq) * QS + kc * 16 + lr * 2;
                uint32_t bh0 = ld32s(kp), bh1 = ld32s(kp + 8);
                uint32_t bl0 = ld32s(kl), bl1 = ld32s(kl + 8);
                mma16(s[nt], ah, bh0, bh1);
                mma16(s[nt], ah, bl0, bl1);
                mma16(s[nt], al, bh0, bh1);
            }
        }

        // ---- scale + causal mask ----
        const bool diag = (kt == qt);
#pragma unroll
        for (int nt = 0; nt < 8; nt++)
#pragma unroll
            for (int cc = 0; cc < 4; cc++) {
                float v = s[nt][cc] * scale;
                if (diag) {
                    int col = nt * 8 + lr * 2 + (cc & 1);
                    int row = wr + lq + ((cc >= 2) ? 8 : 0);
                    if (col > row) v = -INFINITY;
                }
                s[nt][cc] = v;
            }

        // ---- online softmax ----
        float mx0 = m0, mx1 = m1;
#pragma unroll
        for (int nt = 0; nt < 8; nt++) {
            mx0 = fmaxf(mx0, fmaxf(s[nt][0], s[nt][1]));
            mx1 = fmaxf(mx1, fmaxf(s[nt][2], s[nt][3]));
        }
        mx0 = fmaxf(mx0, __shfl_xor_sync(0xffffffffu, mx0, 1));
        mx0 = fmaxf(mx0, __shfl_xor_sync(0xffffffffu, mx0, 2));
        mx1 = fmaxf(mx1, __shfl_xor_sync(0xffffffffu, mx1, 1));
        mx1 = fmaxf(mx1, __shfl_xor_sync(0xffffffffu, mx1, 2));
        float a0 = __expf(m0 - mx0), a1 = __expf(m1 - mx1);
        m0 = mx0; m1 = mx1;
        float sum0 = 0.f, sum1 = 0.f;
#pragma unroll
        for (int nt = 0; nt < 8; nt++) {
            s[nt][0] = __expf(s[nt][0] - mx0);
            s[nt][1] = __expf(s[nt][1] - mx0);
            s[nt][2] = __expf(s[nt][2] - mx1);
            s[nt][3] = __expf(s[nt][3] - mx1);
            sum0 += s[nt][0] + s[nt][1];
            sum1 += s[nt][2] + s[nt][3];
        }
        sum0 += __shfl_xor_sync(0xffffffffu, sum0, 1);
        sum0 += __shfl_xor_sync(0xffffffffu, sum0, 2);
        sum1 += __shfl_xor_sync(0xffffffffu, sum1, 1);
        sum1 += __shfl_xor_sync(0xffffffffu, sum1, 2);
        l0 = l0 * a0 + sum0;
        l1 = l1 * a1 + sum1;

#pragma unroll
        for (int nt = 0; nt < 16; nt++) {
            out[nt][0] *= a0; out[nt][1] *= a0;
            out[nt][2] *= a1; out[nt][3] *= a1;
        }

        // ---- PV (P split to fp16 h/l, V split, 3-pass) ----
#pragma unroll
        for (int kc = 0; kc < 4; kc++) {
            const int t0 = 2 * kc, t1 = 2 * kc + 1;
            uint32_t ph[4], pl[4];
            {
                __half2 h, l;
                h = __floats2half2_rn(s[t0][0], s[t0][1]);
                l = __floats2half2_rn(s[t0][0] - __low2float(h), s[t0][1] - __high2float(h));
                ph[0] = *(uint32_t*)&h; pl[0] = *(uint32_t*)&l;
                h = __floats2half2_rn(s[t0][2], s[t0][3]);
                l = __floats2half2_rn(s[t0][2] - __low2float(h), s[t0][3] - __high2float(h));
                ph[1] = *(uint32_t*)&h; pl[1] = *(uint32_t*)&l;
                h = __floats2half2_rn(s[t1][0], s[t1][1]);
                l = __floats2half2_rn(s[t1][0] - __low2float(h), s[t1][1] - __high2float(h));
                ph[2] = *(uint32_t*)&h; pl[2] = *(uint32_t*)&l;
                h = __floats2half2_rn(s[t1][2], s[t1][3]);
                l = __floats2half2_rn(s[t1][2] - __low2float(h), s[t1][3] - __high2float(h));
                ph[3] = *(uint32_t*)&h; pl[3] = *(uint32_t*)&l;
            }
#pragma unroll
            for (int nt = 0; nt < 16; nt++) {
                const __half* vp = Vth + (nt * 8 + lq) * VS + kc * 16 + lr * 2;
                const __half* vl = Vtl + (nt * 8 + lq) * VS + kc * 16 + lr * 2;
                uint32_t bh0 = ld32s(vp), bh1 = ld32s(vp + 8);
                uint32_t bl0 = ld32s(vl), bl1 = ld32s(vl + 8);
                mma16(out[nt], ph, bh0, bh1);
                mma16(out[nt], ph, bl0, bl1);
                mma16(out[nt], pl, bh0, bh1);
            }
        }
    }

    // ---- epilogue: normalize, split to fp16 h/l, store ----
    const float inv0 = 1.f / l0, inv1 = 1.f / l1;
    const int row0 = qt * 64 + wr + lq;
    const size_t o0 = ((size_t)b * SEQ + row0) * HIDD + head * HD;
    const size_t o1 = o0 + 8 * HIDD;
#pragma unroll
    for (int nt = 0; nt < 16; nt++) {
        int c = nt * 8 + lr * 2;
        __half h0, lo0, h1, lo1;
        split16(out[nt][0] * inv0, h0, lo0);
        split16(out[nt][1] * inv0, h1, lo1);
        *(__half2*)(g_atth + o0 + c) = __halves2half2(h0, h1);
        *(__half2*)(g_attl + o0 + c) = __halves2half2(lo0, lo1);
        split16(out[nt][2] * inv1, h0, lo0);
        split16(out[nt][3] * inv1, h1, lo1);
        *(__half2*)(g_atth + o1 + c) = __halves2half2(h0, h1);
        *(__half2*)(g_attl + o1 + c) = __halves2half2(lo0, lo1);
    }
}

// ---------------- RMSNorm (fp32 and/or fp16 h/l outputs) ----------------
__global__ void rmsnorm_k(const float* __restrict__ x, const float* __restrict__ w,
                          float* __restrict__ yf, __half* __restrict__ yh,
                          __half* __restrict__ yl) {
    int tok = blockIdx.x;
    const float* xr = x + (size_t)tok * HIDD;
    float s = 0.f;
    for (int i = threadIdx.x * 4; i < HIDD; i += blockDim.x * 4) {
        float4 v = *(const float4*)(xr + i);
        s += v.x * v.x + v.y * v.y + v.z * v.z + v.w * v.w;
    }
    __shared__ float red[32];
    for (int o = 16; o > 0; o >>= 1) s += __shfl_xor_sync(0xffffffffu, s, o);
    if ((threadIdx.x & 31) == 0) red[threadIdx.x >> 5] = s;
    __syncthreads();
    if (threadIdx.x < 32) {
        float v = (threadIdx.x < (blockDim.x >> 5)) ? red[threadIdx.x] : 0.f;
        for (int o = 4; o > 0; o >>= 1) v += __shfl_xor_sync(0xffffffffu, v, o);
        if (threadIdx.x == 0) red[0] = rsqrtf(v / (float)HIDD + EPS);
    }
    __syncthreads();
    float sc = red[0];
    for (int i = threadIdx.x * 4; i < HIDD; i += blockDim.x * 4) {
        float4 v = *(const float4*)(xr + i);
        float4 wv = *(const float4*)(w + i);
        float4 o;
        o.x = v.x * sc * wv.x; o.y = v.y * sc * wv.y;
        o.z = v.z * sc * wv.z; o.w = v.w * sc * wv.w;
        if (yf) *(float4*)(yf + (size_t)tok * HIDD + i) = o;
        if (yh) {
            size_t idx = (size_t)tok * HIDD + i;
            __half h0, l0h, h1, l1h, h2, l2h, h3, l3h;
            split16(o.x, h0, l0h); split16(o.y, h1, l1h);
            split16(o.z, h2, l2h); split16(o.w, h3, l3h);
            *(__half2*)(yh + idx) = __halves2half2(h0, h1);
            *(__half2*)(yh + idx + 2) = __halves2half2(h2, h3);
            *(__half2*)(yl + idx) = __halves2half2(l0h, l1h);
            *(__half2*)(yl + idx + 2) = __halves2half2(l2h, l3h);
        }
    }
}

// ---------------- weight cvt: fp32 -> fp16 h/l ----------------
__global__ void cvt16_k(const float* __restrict__ s, __half* __restrict__ h,
                        __half* __restrict__ l, size_t n) {
    size_t i = ((size_t)blockIdx.x * blockDim.x + threadIdx.x) * 4;
    if (i >= n) return;
    float4 v = *(const float4*)(s + i);
    __half h0, l0, h1, l1, h2, l2, h3, l3;
    split16(v.x, h0, l0); split16(v.y, h1, l1);
    split16(v.z, h2, l2); split16(v.w, h3, l3);
    *(__half2*)(h + i) = __halves2half2(h0, h1);
    *(__half2*)(h + i + 2) = __halves2half2(h2, h3);
    *(__half2*)(l + i) = __halves2half2(l0, l1);
    *(__half2*)(l + i + 2) = __halves2half2(l2, l3);
}

// ---------------- router ----------------
__global__ void zero_cnt_k() { if (threadIdx.x < NE) g_cnt[threadIdx.x] = 0; }

__global__ void router_k(const float* __restrict__ xn, const float* __restrict__ Wr) {
    const int tok = blockIdx.x;
    __shared__ float xs[HIDD];
    __shared__ float lg[NE];
    for (int i = threadIdx.x * 4; i < HIDD; i += blockDim.x * 4)
        *(float4*)(xs + i) = *(const float4*)(xn + (size_t)tok * HIDD + i);
    __syncthreads();
    const int w = threadIdx.x >> 5, lane = threadIdx.x & 31;
    const float* wr = Wr + (size_t)w * HIDD;
    float s = 0.f;
    for (int i = lane * 4; i < HIDD; i += 128) {
        float4 a = *(const float4*)(xs + i);
        float4 bb = *(const float4*)(wr + i);
        s += a.x * bb.x + a.y * bb.y + a.z * bb.z + a.w * bb.w;
    }
    for (int o = 16; o > 0; o >>= 1) s += __shfl_xor_sync(0xffffffffu, s, o);
    if (lane == 0) lg[w] = s;
    __syncthreads();
    if (threadIdx.x == 0) {
        float b1 = -INFINITY; int i1 = 0;
        for (int e = 0; e < NE; e++) if (lg[e] > b1) { b1 = lg[e]; i1 = e; }
        float b2 = -INFINITY; int i2 = (i1 == 0) ? 1 : 0;
        for (int e = 0; e < NE; e++) if (e != i1 && lg[e] > b2) { b2 = lg[e]; i2 = e; }
        float eo = expf(b2 - b1);
        float w1 = 1.f / (1.f + eo);
        float w2 = eo / (1.f + eo);
        int p1 = atomicAdd(&g_cnt[i1], 1);
        int p2 = atomicAdd(&g_cnt[i2], 1);
        g_gather[i1 * CAP + p1] = tok;
        g_gather[i2 * CAP + p2] = tok;
        g_slots[tok] = make_int2(i1 * CAP + p1, i2 * CAP + p2);
        g_wts[tok] = make_float2(w1, w2);
    }
}

// ---------------- SwiGLU ----------------
__global__ void silu_mul_k() {
    const int e = blockIdx.y;
    const int m = blockIdx.x;
    if (m >= g_cnt[e]) return;
    const size_t base = ((size_t)e * CAP + m) * INTER;
    for (int i = threadIdx.x * 4; i < INTER; i += blockDim.x * 4) {
        float4 g = *(float4*)(g_hg + base + i);
        float4 u = *(float4*)(g_hu + base + i);
        g.x = g.x / (1.f + __expf(-g.x)) * u.x;
        g.y = g.y / (1.f + __expf(-g.y)) * u.y;
        g.z = g.z / (1.f + __expf(-g.z)) * u.z;
        g.w = g.w / (1.f + __expf(-g.w)) * u.w;
        *(float4*)(g_hg + base + i) = g;
    }
}

// ---------------- final combine ----------------
__global__ void combine_k(const float* __restrict__ x2, float* __restrict__ out) {
    const int tok = blockIdx.x;
    const int2 sl = g_slots[tok];
    const float2 w = g_wts[tok];
    const float* y1 = g_yb + (size_t)sl.x * HIDD;
    const float* y2 = g_yb + (size_t)sl.y * HIDD;
    for (int i = threadIdx.x * 4; i < HIDD; i += blockDim.x * 4) {
        float4 a = *(const float4*)(x2 + (size_t)tok * HIDD + i);
        float4 b = *(const float4*)(y1 + i);
        float4 c = *(const float4*)(y2 + i);
        float4 o;
        o.x = a.x + w.x * b.x + w.y * c.x;
        o.y = a.y + w.x * b.y + w.y * c.y;
        o.z = a.z + w.x * b.z + w.y * c.z;
        o.w = a.w + w.x * b.w + w.y * c.w;
        *(float4*)(out + (size_t)tok * HIDD + i) = o;
    }
}

// ---------------- launch ----------------
extern "C" void kernel_launch(void* const* d_in, const int* in_sizes, int n_in,
                              void* d_out, int out_size) {
    (void)in_sizes; (void)n_in; (void)out_size;
    const float* x    = (const float*)d_in[0];
    const float* Wq   = (const float*)d_in[1];
    const float* Wk   = (const float*)d_in[2];
    const float* Wv   = (const float*)d_in[3];
    const float* Wo   = (const float*)d_in[4];
    const float* wln1 = (const float*)d_in[5];
    const float* wln2 = (const float*)d_in[6];
    const float* Wr   = (const float*)d_in[7];
    const float* Wg   = (const float*)d_in[8];
    const float* Wu   = (const float*)d_in[9];
    const float* Wd   = (const float*)d_in[10];
    float* out = (float*)d_out;

    void* p;
#define SYM(var, sym) cudaGetSymbolAddress(&p, sym); var = (decltype(var))p
    __half *xn1h, *xn1l, *qkvh, *qkvl, *atth, *attl, *wqkvh, *wqkvl, *woh, *wol;
    float *x2, *xn2, *hg, *hu, *yb;
    SYM(xn1h, g_xn1h); SYM(xn1l, g_xn1l);
    SYM(qkvh, g_qkvh); SYM(qkvl, g_qkvl);
    SYM(atth, g_atth); SYM(attl, g_attl);
    SYM(wqkvh, g_wqkvh); SYM(wqkvl, g_wqkvl);
    SYM(woh, g_woh); SYM(wol, g_wol);
    SYM(x2, g_x2); SYM(xn2, g_xn2);
    SYM(hg, g_hg); SYM(hu, g_hu); SYM(yb, g_yb);
#undef SYM

    const int hgemm_smem = 8 * HTILE * 2;   // 81920
    cudaFuncSetAttribute(hgemm<true>,  cudaFuncAttributeMaxDynamicSharedMemorySize, hgemm_smem);
    cudaFuncSetAttribute(hgemm<false>, cudaFuncAttributeMaxDynamicSharedMemorySize, hgemm_smem);
    cudaFuncSetAttribute(flash_mma_k, cudaFuncAttributeMaxDynamicSharedMemorySize, FLASH_SMEM);

    const size_t HH = (size_t)HIDD * HIDD;

    // weight prepass: fp32 -> fp16 h/l (fused QKV rows: q|k|v)
    cvt16_k<<<(unsigned)(HH / 1024), 256>>>(Wq, wqkvh, wqkvl, HH);
    cvt16_k<<<(unsigned)(HH / 1024), 256>>>(Wk, wqkvh + HH, wqkvl + HH, HH);
    cvt16_k<<<(unsigned)(HH / 1024), 256>>>(Wv, wqkvh + 2 * HH, wqkvl + 2 * HH, HH);
    cvt16_k<<<(unsigned)(HH / 1024), 256>>>(Wo, woh, wol, HH);

    // 1) ln1 -> fp16 h/l
    rmsnorm_k<<<T_TOK, 256>>>(x, wln1, nullptr, xn1h, xn1l);
    // 2) fused QKV projection (epilogue writes fp16 h/l)
    hgemm<true><<<dim3(QKVW / HBN, T_TOK / HBM), 256, hgemm_smem>>>(
        xn1h, xn1l, wqkvh, wqkvl, nullptr, nullptr, qkvh, qkvl, T_TOK, QKVW, HIDD);
    // 3) flash attention (tensor cores, fp16 split)
    flash_mma_k<<<dim3(SEQ / 64, NH, NB), 128, FLASH_SMEM>>>();
    // 4) O projection + residual (fp32 out)
    hgemm<false><<<dim3(HIDD / HBN, T_TOK / HBM), 256, hgemm_smem>>>(
        atth, attl, woh, wol, x, x2, nullptr, nullptr, T_TOK, HIDD, HIDD);
    // 5) ln2 (fp32 for router + MoE)
    rmsnorm_k<<<T_TOK, 256>>>(x2, wln2, xn2, nullptr, nullptr);
    // 6) routing
    zero_cnt_k<<<1, 32>>>();
    router_k<<<T_TOK, 256>>>(xn2, Wr);
    // 7) MoE expert GEMMs (tf32, unchanged from round 2)
    dim3 gg(INTER / TBN, CAP / TBM, NE);
    moe_gemm<true><<<gg, 256>>>(xn2, Wg, hg, INTER, HIDD,
                                0, (size_t)INTER * HIDD, (size_t)CAP * INTER);
    moe_gemm<true><<<gg, 256>>>(xn2, Wu, hu, INTER, HIDD,
                                0, (size_t)INTER * HIDD, (size_t)CAP * INTER);
    silu_mul_k<<<dim3(CAP, NE), 256>>>();
    dim3 gd(HIDD / TBN, CAP / TBM, NE);
    moe_gemm<false><<<gd, 256>>>(hg, Wd, yb, HIDD, INTER,
                                 (size_t)CAP * INTER, (size_t)HIDD * INTER,
                                 (size_t)CAP * HIDD);
    // 8) combine + final residual
    combine_k<<<T_TOK, 256>>>(x2, out);
}

// round 8
// speedup vs baseline: 4.4255x; 1.2462x over previous
#include <cuda_runtime.h>
#include <cuda_fp16.h>
#include <math.h>
#include <stdint.h>

#define T_TOK 4096
#define HIDD  2048
#define NH    16
#define HD    128
#define SEQ   2048
#define NB    2
#define NE    8
#define INTER 4096
#define CAP   4096
#define EPS   1e-5f
#define QKVW  6144

// ---------------- scratch ----------------
__device__ __half g_xn1h[(size_t)T_TOK * HIDD];
__device__ __half g_xn1l[(size_t)T_TOK * HIDD];
__device__ __half g_qkvh[(size_t)T_TOK * QKVW];
__device__ __half g_qkvl[(size_t)T_TOK * QKVW];
__device__ __half g_atth[(size_t)T_TOK * HIDD];
__device__ __half g_attl[(size_t)T_TOK * HIDD];
__device__ float  g_x2  [(size_t)T_TOK * HIDD];
__device__ float  g_xn2 [(size_t)T_TOK * HIDD];
__device__ __half g_xn2h[(size_t)T_TOK * HIDD];
__device__ float  g_hg  [(size_t)NE * CAP * INTER];
__device__ float  g_hu  [(size_t)NE * CAP * INTER];
__device__ __half g_acth[(size_t)NE * CAP * INTER];
__device__ float  g_yb  [(size_t)NE * CAP * HIDD];
__device__ __half g_wqkvh[(size_t)QKVW * HIDD];
__device__ __half g_wqkvl[(size_t)QKVW * HIDD];
__device__ __half g_woh[(size_t)HIDD * HIDD];
__device__ __half g_wol[(size_t)HIDD * HIDD];
__device__ __half g_wgh[(size_t)NE * INTER * HIDD];
__device__ __half g_wuh[(size_t)NE * INTER * HIDD];
__device__ __half g_wdh[(size_t)NE * HIDD * INTER];
__device__ int    g_cnt[NE];
__device__ int    g_gather[NE * CAP];
__device__ int2   g_slots[T_TOK];
__device__ float2 g_wts[T_TOK];

// ---------------- helpers ----------------
__device__ __forceinline__ void mma16(float* c, const uint32_t* a, uint32_t b0, uint32_t b1) {
    asm volatile(
        "mma.sync.aligned.m16n8k16.row.col.f32.f16.f16.f32 "
        "{%0,%1,%2,%3}, {%4,%5,%6,%7}, {%8,%9}, {%0,%1,%2,%3};"
        : "+f"(c[0]), "+f"(c[1]), "+f"(c[2]), "+f"(c[3])
        : "r"(a[0]), "r"(a[1]), "r"(a[2]), "r"(a[3]), "r"(b0), "r"(b1));
}
__device__ __forceinline__ void cp_async16(void* smem, const void* gmem) {
    uint32_t s = (uint32_t)__cvta_generic_to_shared(smem);
    asm volatile("cp.async.cg.shared.global [%0], [%1], 16;\n" :: "r"(s), "l"(gmem));
}
__device__ __forceinline__ void cp_commit() { asm volatile("cp.async.commit_group;\n"); }
__device__ __forceinline__ void cp_wait0()  { asm volatile("cp.async.wait_group 0;\n"); }
__device__ __forceinline__ uint32_t ld32s(const __half* p) { return *(const uint32_t*)p; }
__device__ __forceinline__ void split16(float x, __half& h, __half& l) {
    h = __float2half_rn(x);
    l = __float2half_rn(x - __half2float(h));
}

// =========================================================================
// unified fp16 GEMM: C[M,N] = A[M,K] @ B[N,K]^T
//   SPLIT : 3-pass hi/lo (~fp32 accuracy)       else single-pass fp16
//   MOE   : blockIdx.z = expert, M = g_cnt[e]
//   GATHER: A rows indirected through g_gather
//   EPI16 : write fp16 h/l outputs               else fp32 (+optional resid)
// =========================================================================
#define HBM 128
#define HBN 128
#define HBK 32
#define HS  40
#define HTILE (128 * HS)

template <bool SPLIT, bool MOE, bool GATHER, bool EPI16>
__global__ __launch_bounds__(256)
void hgemm(const __half* __restrict__ Ah, const __half* __restrict__ Al,
           const __half* __restrict__ Bh, const __half* __restrict__ Bl,
           const float* __restrict__ resid, float* __restrict__ Cf,
           __half* __restrict__ Ch, __half* __restrict__ Cl,
           int M, int N, int K, size_t aes, size_t bes, size_t ces) {
    extern __shared__ __half hsm[];
    __shared__ int rows_s[HBM];
    const int t = threadIdx.x, lane = t & 31, wid = t >> 5;
    const int lq = lane >> 2, lr = lane & 3;
    const int rb = (wid >> 2) * 64, cb = (wid & 3) * 32;
    const int bm = blockIdx.y * HBM, bn = blockIdx.x * HBN;

    if (MOE) {
        int e = blockIdx.z;
        M = g_cnt[e];
        if (bm >= M) return;
        Ah += (size_t)e * aes;
        Bh += (size_t)e * bes;
        Cf += (size_t)e * ces;
        if (GATHER && t < HBM) {
            int r = bm + t;
            if (r >= M) r = M - 1;
            rows_s[t] = g_gather[e * CAP + r];
        }
        if (GATHER) __syncthreads();
    }

    constexpr int NARR = SPLIT ? 4 : 2;   // [Ah, (Al), Bh, (Bl)] x 2 bufs
    auto tptr = [&](int arr, int buf) { return hsm + (size_t)(arr * 2 + buf) * HTILE; };
    const int IA_H = 0, IA_L = 1, IB_H = SPLIT ? 2 : 1, IB_L = 3;

    float acc[4][4][4];
#pragma unroll
    for (int i = 0; i < 4; i++)
#pragma unroll
        for (int j = 0; j < 4; j++)
#pragma unroll
            for (int f = 0; f < 4; f++) acc[i][j][f] = 0.f;

    // per-thread load slots: 512 slots (128 rows x 4 segs of 8 halves), 2/thread
    int lrow[2], lsg[2];
    size_t aoff[2], boff[2];
#pragma unroll
    for (int i = 0; i < 2; i++) {
        int slot = t + 256 * i;
        lrow[i] = slot >> 2; lsg[i] = (slot & 3) * 8;
        size_t ar = GATHER ? (size_t)rows_s[lrow[i]] : (size_t)(bm + lrow[i]);
        aoff[i] = ar * K + lsg[i];
        boff[i] = (size_t)(bn + lrow[i]) * K + lsg[i];
    }

    auto issue = [&](int c, int buf) {
        const int k0 = c * HBK;
#pragma unroll
        for (int i = 0; i < 2; i++) {
            __half* d = tptr(0, buf) + lrow[i] * HS + lsg[i];
            cp_async16(tptr(IA_H, buf) + lrow[i] * HS + lsg[i], Ah + aoff[i] + k0);
            cp_async16(tptr(IB_H, buf) + lrow[i] * HS + lsg[i], Bh + boff[i] + k0);
            if (SPLIT) {
                cp_async16(tptr(IA_L, buf) + lrow[i] * HS + lsg[i], Al + aoff[i] + k0);
                cp_async16(tptr(IB_L, buf) + lrow[i] * HS + lsg[i], Bl + boff[i] + k0);
            }
            (void)d;
        }
        cp_commit();
    };

    auto compute = [&](int buf) {
        const __half* tAh = tptr(IA_H, buf);
        const __half* tBh = tptr(IB_H, buf);
        const __half* tAl = tptr(IA_L, buf);
        const __half* tBl = tptr(IB_L, buf);
#pragma unroll
        for (int ks = 0; ks < 2; ks++) {
            const int k0 = ks * 16;
            uint32_t ah[4][4], al[4][4], bh[4][2], bl[4][2];
#pragma unroll
            for (int mt = 0; mt < 4; mt++) {
                const __half* p = tAh + (rb + mt * 16 + lq) * HS + k0 + lr * 2;
                ah[mt][0] = ld32s(p);     ah[mt][1] = ld32s(p + 8 * HS);
                ah[mt][2] = ld32s(p + 8); ah[mt][3] = ld32s(p + 8 * HS + 8);
                if (SPLIT) {
                    const __half* q = tAl + (rb + mt * 16 + lq) * HS + k0 + lr * 2;
                    al[mt][0] = ld32s(q);     al[mt][1] = ld32s(q + 8 * HS);
                    al[mt][2] = ld32s(q + 8); al[mt][3] = ld32s(q + 8 * HS + 8);
                }
            }
#pragma unroll
            for (int nt = 0; nt < 4; nt++) {
                const __half* p = tBh + (cb + nt * 8 + lq) * HS + k0 + lr * 2;
                bh[nt][0] = ld32s(p); bh[nt][1] = ld32s(p + 8);
                if (SPLIT) {
                    const __half* q = tBl + (cb + nt * 8 + lq) * HS + k0 + lr * 2;
                    bl[nt][0] = ld32s(q); bl[nt][1] = ld32s(q + 8);
                }
            }
#pragma unroll
            for (int mt = 0; mt < 4; mt++)
#pragma unroll
                for (int nt = 0; nt < 4; nt++) {
                    mma16(acc[mt][nt], ah[mt], bh[nt][0], bh[nt][1]);
                    if (SPLIT) {
                        mma16(acc[mt][nt], ah[mt], bl[nt][0], bl[nt][1]);
                        mma16(acc[mt][nt], al[mt], bh[nt][0], bh[nt][1]);
                    }
                }
        }
    };

    const int nk = K / HBK;
    issue(0, 0);
    cp_wait0();
    __syncthreads();
    for (int c = 0; c < nk; c++) {
        const int cur = c & 1;
        if (c + 1 < nk) issue(c + 1, cur ^ 1);
        compute(cur);
        if (c + 1 < nk) cp_wait0();
        __syncthreads();
    }

#pragma unroll
    for (int mt = 0; mt < 4; mt++)
#pragma unroll
        for (int nt = 0; nt < 4; nt++) {
            int r0g = bm + rb + mt * 16 + lq;
            int r1g = r0g + 8;
            int c0 = bn + cb + nt * 8 + lr * 2;
            if (EPI16) {
                __half h0, l0, h1, l1;
                split16(acc[mt][nt][0], h0, l0); split16(acc[mt][nt][1], h1, l1);
                *(__half2*)(Ch + (size_t)r0g * N + c0) = __halves2half2(h0, h1);
                *(__half2*)(Cl + (size_t)r0g * N + c0) = __halves2half2(l0, l1);
                split16(acc[mt][nt][2], h0, l0); split16(acc[mt][nt][3], h1, l1);
                *(__half2*)(Ch + (size_t)r1g * N + c0) = __halves2half2(h0, h1);
                *(__half2*)(Cl + (size_t)r1g * N + c0) = __halves2half2(l0, l1);
            } else {
                if (!MOE || r0g < M) {
                    float2 v0 = make_float2(acc[mt][nt][0], acc[mt][nt][1]);
                    if (resid) {
                        v0.x += resid[(size_t)r0g * N + c0];
                        v0.y += resid[(size_t)r0g * N + c0 + 1];
                    }
                    *(float2*)(Cf + (size_t)r0g * N + c0) = v0;
                }
                if (!MOE || r1g < M) {
                    float2 v1 = make_float2(acc[mt][nt][2], acc[mt][nt][3]);
                    if (resid) {
                        v1.x += resid[(size_t)r1g * N + c0];
                        v1.y += resid[(size_t)r1g * N + c0 + 1];
                    }
                    *(float2*)(Cf + (size_t)r1g * N + c0) = v1;
                }
            }
        }
}

// =========================================================================
// flash attention: fp16-split mma, causal, 64q x 64k tiles, 4 warps
// =========================================================================
#define QS 136
#define VS 72
#define FLASH_SMEM ((4 * 64 * QS + 2 * 128 * VS) * 2)

__global__ __launch_bounds__(128)
void flash_mma_k() {
    extern __shared__ __half fsm[];
    __half* Qh  = fsm;
    __half* Ql  = Qh + 64 * QS;
    __half* Kh  = Ql + 64 * QS;
    __half* Kl  = Kh + 64 * QS;
    __half* Vth = Kl + 64 * QS;
    __half* Vtl = Vth + 128 * VS;

    const int qt = blockIdx.x, head = blockIdx.y, b = blockIdx.z;
    const int t = threadIdx.x, wid = t >> 5, lane = t & 31;
    const int lq = lane >> 2, lr = lane & 3;
    const int wr = wid * 16;
    const float scale = 0.08838834764831845f;
    const size_t base = (size_t)b * SEQ * QKVW;
    const size_t qoff = (size_t)head * HD;
    const size_t koff = 2048 + qoff, voff = 4096 + qoff;

    for (int i = t; i < 64 * 16; i += 128) {
        int r = i >> 4, sg = (i & 15) * 8;
        size_t g = base + (size_t)(qt * 64 + r) * QKVW + qoff + sg;
        *(uint4*)(Qh + r * QS + sg) = *(const uint4*)(g_qkvh + g);
        *(uint4*)(Ql + r * QS + sg) = *(const uint4*)(g_qkvl + g);
    }

    float out[16][4];
#pragma unroll
    for (int i = 0; i < 16; i++)
#pragma unroll
        for (int j = 0; j < 4; j++) out[i][j] = 0.f;
    float m0 = -INFINITY, m1 = -INFINITY, l0 = 0.f, l1 = 0.f;

    for (int kt = 0; kt <= qt; kt++) {
        __syncthreads();
        for (int i = t; i < 64 * 16; i += 128) {
            int r = i >> 4, sg = (i & 15) * 8;
            size_t g = base + (size_t)(kt * 64 + r) * QKVW + koff + sg;
            *(uint4*)(Kh + r * QS + sg) = *(const uint4*)(g_qkvh + g);
            *(uint4*)(Kl + r * QS + sg) = *(const uint4*)(g_qkvl + g);
        }
        for (int i = t; i < 64 * 64; i += 128) {
            int r = i >> 6, dp = i & 63;
            size_t g = base + (size_t)(kt * 64 + r) * QKVW + voff + dp * 2;
            __half2 vh = *(const __half2*)(g_qkvh + g);
            __half2 vl = *(const __half2*)(g_qkvl + g);
            Vth[(2 * dp) * VS + r]     = __low2half(vh);
            Vth[(2 * dp + 1) * VS + r] = __high2half(vh);
            Vtl[(2 * dp) * VS + r]     = __low2half(vl);
            Vtl[(2 * dp + 1) * VS + r] = __high2half(vl);
        }
        __syncthreads();

        float s[8][4];
#pragma unroll
        for (int i = 0; i < 8; i++)
#pragma unroll
            for (int j = 0; j < 4; j++) s[i][j] = 0.f;

        for (int kc = 0; kc < 8; kc++) {
            uint32_t ah[4], al[4];
            const __half* qp = Qh + (wr + lq) * QS + kc * 16 + lr * 2;
            const __half* ql = Ql + (wr + lq) * QS + kc * 16 + lr * 2;
            ah[0] = ld32s(qp);     ah[1] = ld32s(qp + 8 * QS);
            ah[2] = ld32s(qp + 8); ah[3] = ld32s(qp + 8 * QS + 8);
            al[0] = ld32s(ql);     al[1] = ld32s(ql + 8 * QS);
            al[2] = ld32s(ql + 8); al[3] = ld32s(ql + 8 * QS + 8);
#pragma unroll
            for (int nt = 0; nt < 8; nt++) {
                const __half* kp = Kh + (nt * 8 + lq) * QS + kc * 16 + lr * 2;
                const __half* kl = Kl + (nt * 8 + lq) * QS + kc * 16 + lr * 2;
                uint32_t bh0 = ld32s(kp), bh1 = ld32s(kp + 8);
                uint32_t bl0 = ld32s(kl), bl1 = ld32s(kl + 8);
                mma16(s[nt], ah, bh0, bh1);
                mma16(s[nt], ah, bl0, bl1);
                mma16(s[nt], al, bh0, bh1);
            }
        }

        const bool diag = (kt == qt);
#pragma unroll
        for (int nt = 0; nt < 8; nt++)
#pragma unroll
            for (int cc = 0; cc < 4; cc++) {
                float v = s[nt][cc] * scale;
                if (diag) {
                    int col = nt * 8 + lr * 2 + (cc & 1);
                    int row = wr + lq + ((cc >= 2) ? 8 : 0);
                    if (col > row) v = -INFINITY;
                }
                s[nt][cc] = v;
            }

        float mx0 = m0, mx1 = m1;
#pragma unroll
        for (int nt = 0; nt < 8; nt++) {
            mx0 = fmaxf(mx0, fmaxf(s[nt][0], s[nt][1]));
            mx1 = fmaxf(mx1, fmaxf(s[nt][2], s[nt][3]));
        }
        mx0 = fmaxf(mx0, __shfl_xor_sync(0xffffffffu, mx0, 1));
        mx0 = fmaxf(mx0, __shfl_xor_sync(0xffffffffu, mx0, 2));
        mx1 = fmaxf(mx1, __shfl_xor_sync(0xffffffffu, mx1, 1));
        mx1 = fmaxf(mx1, __shfl_xor_sync(0xffffffffu, mx1, 2));
        float a0 = __expf(m0 - mx0), a1 = __expf(m1 - mx1);
        m0 = mx0; m1 = mx1;
        float sum0 = 0.f, sum1 = 0.f;
#pragma unroll
        for (int nt = 0; nt < 8; nt++) {
            s[nt][0] = __expf(s[nt][0] - mx0);
            s[nt][1] = __expf(s[nt][1] - mx0);
            s[nt][2] = __expf(s[nt][2] - mx1);
            s[nt][3] = __expf(s[nt][3] - mx1);
            sum0 += s[nt][0] + s[nt][1];
            sum1 += s[nt][2] + s[nt][3];
        }
        sum0 += __shfl_xor_sync(0xffffffffu, sum0, 1);
        sum0 += __shfl_xor_sync(0xffffffffu, sum0, 2);
        sum1 += __shfl_xor_sync(0xffffffffu, sum1, 1);
        sum1 += __shfl_xor_sync(0xffffffffu, sum1, 2);
        l0 = l0 * a0 + sum0;
        l1 = l1 * a1 + sum1;

#pragma unroll
        for (int nt = 0; nt < 16; nt++) {
            out[nt][0] *= a0; out[nt][1] *= a0;
            out[nt][2] *= a1; out[nt][3] *= a1;
        }

#pragma unroll
        for (int kc = 0; kc < 4; kc++) {
            const int t0 = 2 * kc, t1 = 2 * kc + 1;
            uint32_t ph[4], pl[4];
            {
                __half2 h, l;
                h = __floats2half2_rn(s[t0][0], s[t0][1]);
                l = __floats2half2_rn(s[t0][0] - __low2float(h), s[t0][1] - __high2float(h));
                ph[0] = *(uint32_t*)&h; pl[0] = *(uint32_t*)&l;
                h = __floats2half2_rn(s[t0][2], s[t0][3]);
                l = __floats2half2_rn(s[t0][2] - __low2float(h), s[t0][3] - __high2float(h));
                ph[1] = *(uint32_t*)&h; pl[1] = *(uint32_t*)&l;
                h = __floats2half2_rn(s[t1][0], s[t1][1]);
                l = __floats2half2_rn(s[t1][0] - __low2float(h), s[t1][1] - __high2float(h));
                ph[2] = *(uint32_t*)&h; pl[2] = *(uint32_t*)&l;
                h = __floats2half2_rn(s[t1][2], s[t1][3]);
                l = __floats2half2_rn(s[t1][2] - __low2float(h), s[t1][3] - __high2float(h));
                ph[3] = *(uint32_t*)&h; pl[3] = *(uint32_t*)&l;
            }
#pragma unroll
            for (int nt = 0; nt < 16; nt++) {
                const __half* vp = Vth + (nt * 8 + lq) * VS + kc * 16 + lr * 2;
                const __half* vl = Vtl + (nt * 8 + lq) * VS + kc * 16 + lr * 2;
                uint32_t bh0 = ld32s(vp), bh1 = ld32s(vp + 8);
                uint32_t bl0 = ld32s(vl), bl1 = ld32s(vl + 8);
                mma16(out[nt], ph, bh0, bh1);
                mma16(out[nt], ph, bl0, bl1);
                mma16(out[nt], pl, bh0, bh1);
            }
        }
    }

    const float inv0 = 1.f / l0, inv1 = 1.f / l1;
    const int row0 = qt * 64 + wr + lq;
    const size_t o0 = ((size_t)b * SEQ + row0) * HIDD + head * HD;
    const size_t o1 = o0 + 8 * HIDD;
#pragma unroll
    for (int nt = 0; nt < 16; nt++) {
        int c = nt * 8 + lr * 2;
        __half h0, lo0, h1, lo1;
        split16(out[nt][0] * inv0, h0, lo0);
        split16(out[nt][1] * inv0, h1, lo1);
        *(__half2*)(g_atth + o0 + c) = __halves2half2(h0, h1);
        *(__half2*)(g_attl + o0 + c) = __halves2half2(lo0, lo1);
        split16(out[nt][2] * inv1, h0, lo0);
        split16(out[nt][3] * inv1, h1, lo1);
        *(__half2*)(g_atth + o1 + c) = __halves2half2(h0, h1);
        *(__half2*)(g_attl + o1 + c) = __halves2half2(lo0, lo1);
    }
}

// ---------------- RMSNorm ----------------
__global__ void rmsnorm_k(const float* __restrict__ x, const float* __restrict__ w,
                          float* __restrict__ yf, __half* __restrict__ yh,
                          __half* __restrict__ yl) {
    int tok = blockIdx.x;
    const float* xr = x + (size_t)tok * HIDD;
    float s = 0.f;
    for (int i = threadIdx.x * 4; i < HIDD; i += blockDim.x * 4) {
        float4 v = *(const float4*)(xr + i);
        s += v.x * v.x + v.y * v.y + v.z * v.z + v.w * v.w;
    }
    __shared__ float red[32];
    for (int o = 16; o > 0; o >>= 1) s += __shfl_xor_sync(0xffffffffu, s, o);
    if ((threadIdx.x & 31) == 0) red[threadIdx.x >> 5] = s;
    __syncthreads();
    if (threadIdx.x < 32) {
        float v = (threadIdx.x < (blockDim.x >> 5)) ? red[threadIdx.x] : 0.f;
        for (int o = 4; o > 0; o >>= 1) v += __shfl_xor_sync(0xffffffffu, v, o);
        if (threadIdx.x == 0) red[0] = rsqrtf(v / (float)HIDD + EPS);
    }
    __syncthreads();
    float sc = red[0];
    for (int i = threadIdx.x * 4; i < HIDD; i += blockDim.x * 4) {
        float4 v = *(const float4*)(xr + i);
        float4 wv = *(const float4*)(w + i);
        float4 o;
        o.x = v.x * sc * wv.x; o.y = v.y * sc * wv.y;
        o.z = v.z * sc * wv.z; o.w = v.w * sc * wv.w;
        size_t idx = (size_t)tok * HIDD + i;
        if (yf) *(float4*)(yf + idx) = o;
        if (yh) {
            __half h0, l0h, h1, l1h, h2, l2h, h3, l3h;
            split16(o.x, h0, l0h); split16(o.y, h1, l1h);
            split16(o.z, h2, l2h); split16(o.w, h3, l3h);
            *(__half2*)(yh + idx) = __halves2half2(h0, h1);
            *(__half2*)(yh + idx + 2) = __halves2half2(h2, h3);
            if (yl) {
                *(__half2*)(yl + idx) = __halves2half2(l0h, l1h);
                *(__half2*)(yl + idx + 2) = __halves2half2(l2h, l3h);
            }
        }
    }
}

// ---------------- weight cvt ----------------
__global__ void cvt16_k(const float* __restrict__ s, __half* __restrict__ h,
                        __half* __restrict__ l, size_t n) {
    size_t i = ((size_t)blockIdx.x * blockDim.x + threadIdx.x) * 4;
    if (i >= n) return;
    float4 v = *(const float4*)(s + i);
    __half h0, l0, h1, l1, h2, l2, h3, l3;
    split16(v.x, h0, l0); split16(v.y, h1, l1);
    split16(v.z, h2, l2); split16(v.w, h3, l3);
    *(__half2*)(h + i) = __halves2half2(h0, h1);
    *(__half2*)(h + i + 2) = __halves2half2(h2, h3);
    *(__half2*)(l + i) = __halves2half2(l0, l1);
    *(__half2*)(l + i + 2) = __halves2half2(l2, l3);
}

__global__ void cvt16h_k(const float* __restrict__ s, __half* __restrict__ h, size_t n) {
    size_t i = ((size_t)blockIdx.x * blockDim.x + threadIdx.x) * 4;
    if (i >= n) return;
    float4 v = *(const float4*)(s + i);
    *(__half2*)(h + i) = __floats2half2_rn(v.x, v.y);
    *(__half2*)(h + i + 2) = __floats2half2_rn(v.z, v.w);
}

// ---------------- router ----------------
__global__ void zero_cnt_k() { if (threadIdx.x < NE) g_cnt[threadIdx.x] = 0; }

__global__ void router_k(const float* __restrict__ xn, const float* __restrict__ Wr) {
    const int tok = blockIdx.x;
    __shared__ float xs[HIDD];
    __shared__ float lg[NE];
    for (int i = threadIdx.x * 4; i < HIDD; i += blockDim.x * 4)
        *(float4*)(xs + i) = *(const float4*)(xn + (size_t)tok * HIDD + i);
    __syncthreads();
    const int w = threadIdx.x >> 5, lane = threadIdx.x & 31;
    const float* wr = Wr + (size_t)w * HIDD;
    float s = 0.f;
    for (int i = lane * 4; i < HIDD; i += 128) {
        float4 a = *(const float4*)(xs + i);
        float4 bb = *(const float4*)(wr + i);
        s += a.x * bb.x + a.y * bb.y + a.z * bb.z + a.w * bb.w;
    }
    for (int o = 16; o > 0; o >>= 1) s += __shfl_xor_sync(0xffffffffu, s, o);
    if (lane == 0) lg[w] = s;
    __syncthreads();
    if (threadIdx.x == 0) {
        float b1 = -INFINITY; int i1 = 0;
        for (int e = 0; e < NE; e++) if (lg[e] > b1) { b1 = lg[e]; i1 = e; }
        float b2 = -INFINITY; int i2 = (i1 == 0) ? 1 : 0;
        for (int e = 0; e < NE; e++) if (e != i1 && lg[e] > b2) { b2 = lg[e]; i2 = e; }
        float eo = expf(b2 - b1);
        float w1 = 1.f / (1.f + eo);
        float w2 = eo / (1.f + eo);
        int p1 = atomicAdd(&g_cnt[i1], 1);
        int p2 = atomicAdd(&g_cnt[i2], 1);
        g_gather[i1 * CAP + p1] = tok;
        g_gather[i2 * CAP + p2] = tok;
        g_slots[tok] = make_int2(i1 * CAP + p1, i2 * CAP + p2);
        g_wts[tok] = make_float2(w1, w2);
    }
}

// ---------------- SwiGLU: act(fp16) = silu(hg) * hu ----------------
__global__ void silu_mul_k() {
    const int e = blockIdx.y;
    const int m = blockIdx.x;
    if (m >= g_cnt[e]) return;
    const size_t base = ((size_t)e * CAP + m) * INTER;
    for (int i = threadIdx.x * 4; i < INTER; i += blockDim.x * 4) {
        float4 g = *(float4*)(g_hg + base + i);
        float4 u = *(float4*)(g_hu + base + i);
        float a0 = g.x / (1.f + __expf(-g.x)) * u.x;
        float a1 = g.y / (1.f + __expf(-g.y)) * u.y;
        float a2 = g.z / (1.f + __expf(-g.z)) * u.z;
        float a3 = g.w / (1.f + __expf(-g.w)) * u.w;
        *(__half2*)(g_acth + base + i) = __floats2half2_rn(a0, a1);
        *(__half2*)(g_acth + base + i + 2) = __floats2half2_rn(a2, a3);
    }
}

// ---------------- final combine ----------------
__global__ void combine_k(const float* __restrict__ x2, float* __restrict__ out) {
    const int tok = blockIdx.x;
    const int2 sl = g_slots[tok];
    const float2 w = g_wts[tok];
    const float* y1 = g_yb + (size_t)sl.x * HIDD;
    const float* y2 = g_yb + (size_t)sl.y * HIDD;
    for (int i = threadIdx.x * 4; i < HIDD; i += blockDim.x * 4) {
        float4 a = *(const float4*)(x2 + (size_t)tok * HIDD + i);
        float4 b = *(const float4*)(y1 + i);
        float4 c = *(const float4*)(y2 + i);
        float4 o;
        o.x = a.x + w.x * b.x + w.y * c.x;
        o.y = a.y + w.x * b.y + w.y * c.y;
        o.z = a.z + w.x * b.z + w.y * c.z;
        o.w = a.w + w.x * b.w + w.y * c.w;
        *(float4*)(out + (size_t)tok * HIDD + i) = o;
    }
}

// ---------------- launch ----------------
extern "C" void kernel_launch(void* const* d_in, const int* in_sizes, int n_in,
                              void* d_out, int out_size) {
    (void)in_sizes; (void)n_in; (void)out_size;
    const float* x    = (const float*)d_in[0];
    const float* Wq   = (const float*)d_in[1];
    const float* Wk   = (const float*)d_in[2];
    const float* Wv   = (const float*)d_in[3];
    const float* Wo   = (const float*)d_in[4];
    const float* wln1 = (const float*)d_in[5];
    const float* wln2 = (const float*)d_in[6];
    const float* Wr   = (const float*)d_in[7];
    const float* Wg   = (const float*)d_in[8];
    const float* Wu   = (const float*)d_in[9];
    const float* Wd   = (const float*)d_in[10];
    float* out = (float*)d_out;

    void* p;
#define SYM(var, sym) cudaGetSymbolAddress(&p, sym); var = (decltype(var))p
    __half *xn1h, *xn1l, *qkvh, *qkvl, *atth, *attl, *wqkvh, *wqkvl, *woh, *wol;
    __half *xn2h, *wgh, *wuh, *wdh, *acth;
    float *x2, *xn2, *hg, *hu, *yb;
    SYM(xn1h, g_xn1h); SYM(xn1l, g_xn1l);
    SYM(qkvh, g_qkvh); SYM(qkvl, g_qkvl);
    SYM(atth, g_atth); SYM(attl, g_attl);
    SYM(wqkvh, g_wqkvh); SYM(wqkvl, g_wqkvl);
    SYM(woh, g_woh); SYM(wol, g_wol);
    SYM(xn2h, g_xn2h); SYM(wgh, g_wgh); SYM(wuh, g_wuh); SYM(wdh, g_wdh);
    SYM(acth, g_acth);
    SYM(x2, g_x2); SYM(xn2, g_xn2);
    SYM(hg, g_hg); SYM(hu, g_hu); SYM(yb, g_yb);
#undef SYM

    const int split_smem  = 8 * HTILE * 2;   // 81920
    const int single_smem = 4 * HTILE * 2;   // 40960
    cudaFuncSetAttribute((const void*)hgemm<true,  false, false, true>,
                         cudaFuncAttributeMaxDynamicSharedMemorySize, split_smem);
    cudaFuncSetAttribute((const void*)hgemm<true,  false, false, false>,
                         cudaFuncAttributeMaxDynamicSharedMemorySize, split_smem);
    cudaFuncSetAttribute((const void*)hgemm<false, true,  true,  false>,
                         cudaFuncAttributeMaxDynamicSharedMemorySize, single_smem);
    cudaFuncSetAttribute((const void*)hgemm<false, true,  false, false>,
                         cudaFuncAttributeMaxDynamicSharedMemorySize, single_smem);
    cudaFuncSetAttribute(flash_mma_k, cudaFuncAttributeMaxDynamicSharedMemorySize, FLASH_SMEM);

    const size_t HH = (size_t)HIDD * HIDD;
    const size_t EIH = (size_t)NE * INTER * HIDD;

    // weight prepass
    cvt16_k<<<(unsigned)(HH / 1024), 256>>>(Wq, wqkvh, wqkvl, HH);
    cvt16_k<<<(unsigned)(HH / 1024), 256>>>(Wk, wqkvh + HH, wqkvl + HH, HH);
    cvt16_k<<<(unsigned)(HH / 1024), 256>>>(Wv, wqkvh + 2 * HH, wqkvl + 2 * HH, HH);
    cvt16_k<<<(unsigned)(HH / 1024), 256>>>(Wo, woh, wol, HH);
    cvt16h_k<<<(unsigned)(EIH / 1024), 256>>>(Wg, wgh, EIH);
    cvt16h_k<<<(unsigned)(EIH / 1024), 256>>>(Wu, wuh, EIH);
    cvt16h_k<<<(unsigned)(EIH / 1024), 256>>>(Wd, wdh, EIH);

    // 1) ln1 -> fp16 h/l
    rmsnorm_k<<<T_TOK, 256>>>(x, wln1, nullptr, xn1h, xn1l);
    // 2) fused QKV projection (split, fp16 h/l epilogue)
    hgemm<true, false, false, true><<<dim3(QKVW / HBN, T_TOK / HBM), 256, split_smem>>>(
        xn1h, xn1l, wqkvh, wqkvl, nullptr, nullptr, qkvh, qkvl, T_TOK, QKVW, HIDD, 0, 0, 0);
    // 3) flash attention
    flash_mma_k<<<dim3(SEQ / 64, NH, NB), 128, FLASH_SMEM>>>();
    // 4) O projection + residual (split, fp32 out)
    hgemm<true, false, false, false><<<dim3(HIDD / HBN, T_TOK / HBM), 256, split_smem>>>(
        atth, attl, woh, wol, x, x2, nullptr, nullptr, T_TOK, HIDD, HIDD, 0, 0, 0);
    // 5) ln2 -> fp32 (router) + fp16 (experts)
    rmsnorm_k<<<T_TOK, 256>>>(x2, wln2, xn2, xn2h, nullptr);
    // 6) routing
    zero_cnt_k<<<1, 32>>>();
    router_k<<<T_TOK, 256>>>(xn2, Wr);
    // 7) MoE GEMMs — single-pass fp16 (k16, 2x tf32 rate, same 10-bit mantissa)
    dim3 gg(INTER / HBN, CAP / HBM, NE);
    hgemm<false, true, true, false><<<gg, 256, single_smem>>>(
        xn2h, nullptr, wgh, nullptr, nullptr, hg, nullptr, nullptr,
        0, INTER, HIDD, 0, (size_t)INTER * HIDD, (size_t)CAP * INTER);
    hgemm<false, true, true, false><<<gg, 256, single_smem>>>(
        xn2h, nullptr, wuh, nullptr, nullptr, hu, nullptr, nullptr,
        0, INTER, HIDD, 0, (size_t)INTER * HIDD, (size_t)CAP * INTER);
    silu_mul_k<<<dim3(CAP, NE), 256>>>();
    dim3 gd(HIDD / HBN, CAP / HBM, NE);
    hgemm<false, true, false, false><<<gd, 256, single_smem>>>(
        acth, nullptr, wdh, nullptr, nullptr, yb, nullptr, nullptr,
        0, HIDD, INTER, (size_t)CAP * INTER, (size_t)HIDD * INTER, (size_t)CAP * HIDD);
    // 8) combine + final residual
    combine_k<<<T_TOK, 256>>>(x2, out);
}

// round 10
// speedup vs baseline: 4.4981x; 1.0164x over previous
#include <cuda_runtime.h>
#include <cuda_fp16.h>
#include <math.h>
#include <stdint.h>

#define T_TOK 4096
#define HIDD  2048
#define NH    16
#define HD    128
#define SEQ   2048
#define NB    2
#define NE    8
#define INTER 4096
#define CAP   4096
#define EPS   1e-5f
#define QKVW  6144

// ---------------- scratch ----------------
__device__ __half g_xn1h[(size_t)T_TOK * HIDD];
__device__ __half g_xn1l[(size_t)T_TOK * HIDD];
__device__ __half g_qkvh[(size_t)T_TOK * QKVW];
__device__ __half g_qkvl[(size_t)T_TOK * QKVW];
__device__ __half g_atth[(size_t)T_TOK * HIDD];
__device__ __half g_attl[(size_t)T_TOK * HIDD];
__device__ float  g_x2  [(size_t)T_TOK * HIDD];
__device__ float  g_xn2 [(size_t)T_TOK * HIDD];
__device__ __half g_xn2h[(size_t)T_TOK * HIDD];
__device__ __half g_acth[(size_t)NE * CAP * INTER];
__device__ float  g_yb  [(size_t)NE * CAP * HIDD];
__device__ __half g_wqkvh[(size_t)QKVW * HIDD];
__device__ __half g_wqkvl[(size_t)QKVW * HIDD];
__device__ __half g_woh[(size_t)HIDD * HIDD];
__device__ __half g_wol[(size_t)HIDD * HIDD];
__device__ __half g_wguh[(size_t)NE * 2 * INTER * HIDD];  // interleaved gate/up rows
__device__ __half g_wdh[(size_t)NE * HIDD * INTER];
__device__ int    g_cnt[NE];
__device__ int    g_gather[NE * CAP];
__device__ int2   g_slots[T_TOK];
__device__ float2 g_wts[T_TOK];

// ---------------- helpers ----------------
__device__ __forceinline__ void mma16(float* c, const uint32_t* a, uint32_t b0, uint32_t b1) {
    asm volatile(
        "mma.sync.aligned.m16n8k16.row.col.f32.f16.f16.f32 "
        "{%0,%1,%2,%3}, {%4,%5,%6,%7}, {%8,%9}, {%0,%1,%2,%3};"
        : "+f"(c[0]), "+f"(c[1]), "+f"(c[2]), "+f"(c[3])
        : "r"(a[0]), "r"(a[1]), "r"(a[2]), "r"(a[3]), "r"(b0), "r"(b1));
}
__device__ __forceinline__ void ldm_x4(uint32_t* r, uint32_t saddr) {
    asm volatile("ldmatrix.sync.aligned.m8n8.x4.shared.b16 {%0,%1,%2,%3}, [%4];"
                 : "=r"(r[0]), "=r"(r[1]), "=r"(r[2]), "=r"(r[3]) : "r"(saddr));
}
__device__ __forceinline__ void cp_async16(void* smem, const void* gmem) {
    uint32_t s = (uint32_t)__cvta_generic_to_shared(smem);
    asm volatile("cp.async.cg.shared.global [%0], [%1], 16;\n" :: "r"(s), "l"(gmem));
}
__device__ __forceinline__ void cp_commit() { asm volatile("cp.async.commit_group;\n"); }
__device__ __forceinline__ void cp_wait0()  { asm volatile("cp.async.wait_group 0;\n"); }
__device__ __forceinline__ uint32_t ld32s(const __half* p) { return *(const uint32_t*)p; }
__device__ __forceinline__ void split16(float x, __half& h, __half& l) {
    h = __float2half_rn(x);
    l = __float2half_rn(x - __half2float(h));
}

// =========================================================================
// unified fp16 GEMM: C[M,N] = A[M,K] @ B[N,K]^T
//   SPLIT : 3-pass hi/lo        MOE: z=expert   GATHER: A row indirection
//   EPI16 : fp16 h/l out        SWIGLU: N covers interleaved gate/up pairs,
//                                       epilogue writes silu(g)*u as fp16
// =========================================================================
#define HBM 128
#define HBN 128
#define HBK 32
#define HS  40
#define HTILE (128 * HS)

template <bool SPLIT, bool MOE, bool GATHER, bool EPI16, bool SWIGLU>
__global__ __launch_bounds__(256)
void hgemm(const __half* __restrict__ Ah, const __half* __restrict__ Al,
           const __half* __restrict__ Bh, const __half* __restrict__ Bl,
           const float* __restrict__ resid, float* __restrict__ Cf,
           __half* __restrict__ Ch, __half* __restrict__ Cl,
           int M, int N, int K, size_t aes, size_t bes, size_t ces) {
    extern __shared__ __half hsm[];
    __shared__ int rows_s[HBM];
    const int t = threadIdx.x, lane = t & 31, wid = t >> 5;
    const int lq = lane >> 2, lr = lane & 3;
    const int lrow16 = lane & 15, lsel = lane >> 4;
    const int rb = (wid >> 2) * 64, cb = (wid & 3) * 32;
    const int bm = blockIdx.y * HBM, bn = blockIdx.x * HBN;

    if (MOE) {
        int e = blockIdx.z;
        M = g_cnt[e];
        if (bm >= M) return;
        Ah += (size_t)e * aes;
        Bh += (size_t)e * bes;
        if (SWIGLU) Ch += (size_t)e * ces; else Cf += (size_t)e * ces;
        if (GATHER && t < HBM) {
            int r = bm + t;
            if (r >= M) r = M - 1;
            rows_s[t] = g_gather[e * CAP + r];
        }
        if (GATHER) __syncthreads();
    }

    const uint32_t sbase = (uint32_t)__cvta_generic_to_shared(hsm);
    const int IA_H = 0, IA_L = 1, IB_H = SPLIT ? 2 : 1, IB_L = 3;
    auto tgen = [&](int arr, int buf) { return hsm + (size_t)(arr * 2 + buf) * HTILE; };
    auto tsh  = [&](int arr, int buf) { return sbase + (uint32_t)(arr * 2 + buf) * HTILE * 2; };

    float acc[4][4][4];
#pragma unroll
    for (int i = 0; i < 4; i++)
#pragma unroll
        for (int j = 0; j < 4; j++)
#pragma unroll
            for (int f = 0; f < 4; f++) acc[i][j][f] = 0.f;

    int lrow[2], lsg[2];
    size_t aoff[2], boff[2];
#pragma unroll
    for (int i = 0; i < 2; i++) {
        int slot = t + 256 * i;
        lrow[i] = slot >> 2; lsg[i] = (slot & 3) * 8;
        size_t ar = GATHER ? (size_t)rows_s[lrow[i]] : (size_t)(bm + lrow[i]);
        aoff[i] = ar * K + lsg[i];
        boff[i] = (size_t)(bn + lrow[i]) * K + lsg[i];
    }

    auto issue = [&](int c, int buf) {
        const int k0 = c * HBK;
#pragma unroll
        for (int i = 0; i < 2; i++) {
            cp_async16(tgen(IA_H, buf) + lrow[i] * HS + lsg[i], Ah + aoff[i] + k0);
            cp_async16(tgen(IB_H, buf) + lrow[i] * HS + lsg[i], Bh + boff[i] + k0);
            if (SPLIT) {
                cp_async16(tgen(IA_L, buf) + lrow[i] * HS + lsg[i], Al + aoff[i] + k0);
                cp_async16(tgen(IB_L, buf) + lrow[i] * HS + lsg[i], Bl + boff[i] + k0);
            }
        }
        cp_commit();
    };

    auto compute = [&](int buf) {
        const uint32_t tAh = tsh(IA_H, buf), tBh = tsh(IB_H, buf);
        const uint32_t tAl = tsh(IA_L, buf), tBl = tsh(IB_L, buf);
#pragma unroll
        for (int ks = 0; ks < 2; ks++) {
            const int k0 = ks * 16;
            uint32_t ah[4][4], al[4][4], bh[4][2], bl[4][2];
#pragma unroll
            for (int mt = 0; mt < 4; mt++) {
                uint32_t off = (uint32_t)(((rb + mt * 16 + lrow16) * HS + k0 + lsel * 8) * 2);
                ldm_x4(ah[mt], tAh + off);
                if (SPLIT) ldm_x4(al[mt], tAl + off);
            }
#pragma unroll
            for (int np = 0; np < 2; np++) {
                uint32_t off = (uint32_t)(((cb + np * 16 + lrow16) * HS + k0 + lsel * 8) * 2);
                uint32_t r[4];
                ldm_x4(r, tBh + off);
                bh[2 * np][0] = r[0]; bh[2 * np][1] = r[2];
                bh[2 * np + 1][0] = r[1]; bh[2 * np + 1][1] = r[3];
                if (SPLIT) {
                    ldm_x4(r, tBl + off);
                    bl[2 * np][0] = r[0]; bl[2 * np][1] = r[2];
                    bl[2 * np + 1][0] = r[1]; bl[2 * np + 1][1] = r[3];
                }
            }
#pragma unroll
            for (int mt = 0; mt < 4; mt++)
#pragma unroll
                for (int nt = 0; nt < 4; nt++) {
                    mma16(acc[mt][nt], ah[mt], bh[nt][0], bh[nt][1]);
                    if (SPLIT) {
                        mma16(acc[mt][nt], ah[mt], bl[nt][0], bl[nt][1]);
                        mma16(acc[mt][nt], al[mt], bh[nt][0], bh[nt][1]);
                    }
                }
        }
    };

    const int nk = K / HBK;
    issue(0, 0);
    cp_wait0();
    __syncthreads();
    for (int c = 0; c < nk; c++) {
        const int cur = c & 1;
        if (c + 1 < nk) issue(c + 1, cur ^ 1);
        compute(cur);
        if (c + 1 < nk) cp_wait0();
        __syncthreads();
    }

#pragma unroll
    for (int mt = 0; mt < 4; mt++)
#pragma unroll
        for (int nt = 0; nt < 4; nt++) {
            int r0g = bm + rb + mt * 16 + lq;
            int r1g = r0g + 8;
            int c0 = bn + cb + nt * 8 + lr * 2;
            if (SWIGLU) {
                int oc = c0 >> 1;
                if (r0g < M) {
                    float g = acc[mt][nt][0], u = acc[mt][nt][1];
                    Ch[(size_t)r0g * INTER + oc] =
                        __float2half_rn(g / (1.f + __expf(-g)) * u);
                }
                if (r1g < M) {
                    float g = acc[mt][nt][2], u = acc[mt][nt][3];
                    Ch[(size_t)r1g * INTER + oc] =
                        __float2half_rn(g / (1.f + __expf(-g)) * u);
                }
            } else if (EPI16) {
                __half h0, l0, h1, l1;
                split16(acc[mt][nt][0], h0, l0); split16(acc[mt][nt][1], h1, l1);
                *(__half2*)(Ch + (size_t)r0g * N + c0) = __halves2half2(h0, h1);
                *(__half2*)(Cl + (size_t)r0g * N + c0) = __halves2half2(l0, l1);
                split16(acc[mt][nt][2], h0, l0); split16(acc[mt][nt][3], h1, l1);
                *(__half2*)(Ch + (size_t)r1g * N + c0) = __halves2half2(h0, h1);
                *(__half2*)(Cl + (size_t)r1g * N + c0) = __halves2half2(l0, l1);
            } else {
                if (!MOE || r0g < M) {
                    float2 v0 = make_float2(acc[mt][nt][0], acc[mt][nt][1]);
                    if (resid) {
                        v0.x += resid[(size_t)r0g * N + c0];
                        v0.y += resid[(size_t)r0g * N + c0 + 1];
                    }
                    *(float2*)(Cf + (size_t)r0g * N + c0) = v0;
                }
                if (!MOE || r1g < M) {
                    float2 v1 = make_float2(acc[mt][nt][2], acc[mt][nt][3]);
                    if (resid) {
                        v1.x += resid[(size_t)r1g * N + c0];
                        v1.y += resid[(size_t)r1g * N + c0 + 1];
                    }
                    *(float2*)(Cf + (size_t)r1g * N + c0) = v1;
                }
            }
        }
}

// =========================================================================
// flash attention: fp16-split mma, causal, 64q x 64k tiles, 4 warps
// =========================================================================
#define QS 136
#define VS 72
#define FLASH_SMEM ((4 * 64 * QS + 2 * 128 * VS) * 2)

__global__ __launch_bounds__(128)
void flash_mma_k() {
    extern __shared__ __half fsm[];
    __half* Qh  = fsm;
    __half* Ql  = Qh + 64 * QS;
    __half* Kh  = Ql + 64 * QS;
    __half* Kl  = Kh + 64 * QS;
    __half* Vth = Kl + 64 * QS;
    __half* Vtl = Vth + 128 * VS;

    const int qt = blockIdx.x, head = blockIdx.y, b = blockIdx.z;
    const int t = threadIdx.x, wid = t >> 5, lane = t & 31;
    const int lq = lane >> 2, lr = lane & 3;
    const int wr = wid * 16;
    const float scale = 0.08838834764831845f;
    const size_t base = (size_t)b * SEQ * QKVW;
    const size_t qoff = (size_t)head * HD;
    const size_t koff = 2048 + qoff, voff = 4096 + qoff;

    for (int i = t; i < 64 * 16; i += 128) {
        int r = i >> 4, sg = (i & 15) * 8;
        size_t g = base + (size_t)(qt * 64 + r) * QKVW + qoff + sg;
        *(uint4*)(Qh + r * QS + sg) = *(const uint4*)(g_qkvh + g);
        *(uint4*)(Ql + r * QS + sg) = *(const uint4*)(g_qkvl + g);
    }

    float out[16][4];
#pragma unroll
    for (int i = 0; i < 16; i++)
#pragma unroll
        for (int j = 0; j < 4; j++) out[i][j] = 0.f;
    float m0 = -INFINITY, m1 = -INFINITY, l0 = 0.f, l1 = 0.f;

    for (int kt = 0; kt <= qt; kt++) {
        __syncthreads();
        for (int i = t; i < 64 * 16; i += 128) {
            int r = i >> 4, sg = (i & 15) * 8;
            size_t g = base + (size_t)(kt * 64 + r) * QKVW + koff + sg;
            *(uint4*)(Kh + r * QS + sg) = *(const uint4*)(g_qkvh + g);
            *(uint4*)(Kl + r * QS + sg) = *(const uint4*)(g_qkvl + g);
        }
        for (int i = t; i < 64 * 64; i += 128) {
            int r = i >> 6, dp = i & 63;
            size_t g = base + (size_t)(kt * 64 + r) * QKVW + voff + dp * 2;
            __half2 vh = *(const __half2*)(g_qkvh + g);
            __half2 vl = *(const __half2*)(g_qkvl + g);
            Vth[(2 * dp) * VS + r]     = __low2half(vh);
            Vth[(2 * dp + 1) * VS + r] = __high2half(vh);
            Vtl[(2 * dp) * VS + r]     = __low2half(vl);
            Vtl[(2 * dp + 1) * VS + r] = __high2half(vl);
        }
        __syncthreads();

        float s[8][4];
#pragma unroll
        for (int i = 0; i < 8; i++)
#pragma unroll
            for (int j = 0; j < 4; j++) s[i][j] = 0.f;

        for (int kc = 0; kc < 8; kc++) {
            uint32_t ah[4], al[4];
            const __half* qp = Qh + (wr + lq) * QS + kc * 16 + lr * 2;
            const __half* ql = Ql + (wr + lq) * QS + kc * 16 + lr * 2;
            ah[0] = ld32s(qp);     ah[1] = ld32s(qp + 8 * QS);
            ah[2] = ld32s(qp + 8); ah[3] = ld32s(qp + 8 * QS + 8);
            al[0] = ld32s(ql);     al[1] = ld32s(ql + 8 * QS);
            al[2] = ld32s(ql + 8); al[3] = ld32s(ql + 8 * QS + 8);
#pragma unroll
            for (int nt = 0; nt < 8; nt++) {
                const __half* kp = Kh + (nt * 8 + lq) * QS + kc * 16 + lr * 2;
                const __half* kl = Kl + (nt * 8 + lq) * QS + kc * 16 + lr * 2;
                uint32_t bh0 = ld32s(kp), bh1 = ld32s(kp + 8);
                uint32_t bl0 = ld32s(kl), bl1 = ld32s(kl + 8);
                mma16(s[nt], ah, bh0, bh1);
                mma16(s[nt], ah, bl0, bl1);
                mma16(s[nt], al, bh0, bh1);
            }
        }

        const bool diag = (kt == qt);
#pragma unroll
        for (int nt = 0; nt < 8; nt++)
#pragma unroll
            for (int cc = 0; cc < 4; cc++) {
                float v = s[nt][cc] * scale;
                if (diag) {
                    int col = nt * 8 + lr * 2 + (cc & 1);
                    int row = wr + lq + ((cc >= 2) ? 8 : 0);
                    if (col > row) v = -INFINITY;
                }
                s[nt][cc] = v;
            }

        float mx0 = m0, mx1 = m1;
#pragma unroll
        for (int nt = 0; nt < 8; nt++) {
            mx0 = fmaxf(mx0, fmaxf(s[nt][0], s[nt][1]));
            mx1 = fmaxf(mx1, fmaxf(s[nt][2], s[nt][3]));
        }
        mx0 = fmaxf(mx0, __shfl_xor_sync(0xffffffffu, mx0, 1));
        mx0 = fmaxf(mx0, __shfl_xor_sync(0xffffffffu, mx0, 2));
        mx1 = fmaxf(mx1, __shfl_xor_sync(0xffffffffu, mx1, 1));
        mx1 = fmaxf(mx1, __shfl_xor_sync(0xffffffffu, mx1, 2));
        float a0 = __expf(m0 - mx0), a1 = __expf(m1 - mx1);
        m0 = mx0; m1 = mx1;
        float sum0 = 0.f, sum1 = 0.f;
#pragma unroll
        for (int nt = 0; nt < 8; nt++) {
            s[nt][0] = __expf(s[nt][0] - mx0);
            s[nt][1] = __expf(s[nt][1] - mx0);
            s[nt][2] = __expf(s[nt][2] - mx1);
            s[nt][3] = __expf(s[nt][3] - mx1);
            sum0 += s[nt][0] + s[nt][1];
            sum1 += s[nt][2] + s[nt][3];
        }
        sum0 += __shfl_xor_sync(0xffffffffu, sum0, 1);
        sum0 += __shfl_xor_sync(0xffffffffu, sum0, 2);
        sum1 += __shfl_xor_sync(0xffffffffu, sum1, 1);
        sum1 += __shfl_xor_sync(0xffffffffu, sum1, 2);
        l0 = l0 * a0 + sum0;
        l1 = l1 * a1 + sum1;

#pragma unroll
        for (int nt = 0; nt < 16; nt++) {
            out[nt][0] *= a0; out[nt][1] *= a0;
            out[nt][2] *= a1; out[nt][3] *= a1;
        }

#pragma unroll
        for (int kc = 0; kc < 4; kc++) {
            const int t0 = 2 * kc, t1 = 2 * kc + 1;
            uint32_t ph[4], pl[4];
            {
                __half2 h, l;
                h = __floats2half2_rn(s[t0][0], s[t0][1]);
                l = __floats2half2_rn(s[t0][0] - __low2float(h), s[t0][1] - __high2float(h));
                ph[0] = *(uint32_t*)&h; pl[0] = *(uint32_t*)&l;
                h = __floats2half2_rn(s[t0][2], s[t0][3]);
                l = __floats2half2_rn(s[t0][2] - __low2float(h), s[t0][3] - __high2float(h));
                ph[1] = *(uint32_t*)&h; pl[1] = *(uint32_t*)&l;
                h = __floats2half2_rn(s[t1][0], s[t1][1]);
                l = __floats2half2_rn(s[t1][0] - __low2float(h), s[t1][1] - __high2float(h));
                ph[2] = *(uint32_t*)&h; pl[2] = *(uint32_t*)&l;
                h = __floats2half2_rn(s[t1][2], s[t1][3]);
                l = __floats2half2_rn(s[t1][2] - __low2float(h), s[t1][3] - __high2float(h));
                ph[3] = *(uint32_t*)&h; pl[3] = *(uint32_t*)&l;
            }
#pragma unroll
            for (int nt = 0; nt < 16; nt++) {
                const __half* vp = Vth + (nt * 8 + lq) * VS + kc * 16 + lr * 2;
                const __half* vl = Vtl + (nt * 8 + lq) * VS + kc * 16 + lr * 2;
                uint32_t bh0 = ld32s(vp), bh1 = ld32s(vp + 8);
                uint32_t bl0 = ld32s(vl), bl1 = ld32s(vl + 8);
                mma16(out[nt], ph, bh0, bh1);
                mma16(out[nt], ph, bl0, bl1);
                mma16(out[nt], pl, bh0, bh1);
            }
        }
    }

    const float inv0 = 1.f / l0, inv1 = 1.f / l1;
    const int row0 = qt * 64 + wr + lq;
    const size_t o0 = ((size_t)b * SEQ + row0) * HIDD + head * HD;
    const size_t o1 = o0 + 8 * HIDD;
#pragma unroll
    for (int nt = 0; nt < 16; nt++) {
        int c = nt * 8 + lr * 2;
        __half h0, lo0, h1, lo1;
        split16(out[nt][0] * inv0, h0, lo0);
        split16(out[nt][1] * inv0, h1, lo1);
        *(__half2*)(g_atth + o0 + c) = __halves2half2(h0, h1);
        *(__half2*)(g_attl + o0 + c) = __halves2half2(lo0, lo1);
        split16(out[nt][2] * inv1, h0, lo0);
        split16(out[nt][3] * inv1, h1, lo1);
        *(__half2*)(g_atth + o1 + c) = __halves2half2(h0, h1);
        *(__half2*)(g_attl + o1 + c) = __halves2half2(lo0, lo1);
    }
}

// ---------------- RMSNorm ----------------
__global__ void rmsnorm_k(const float* __restrict__ x, const float* __restrict__ w,
                          float* __restrict__ yf, __half* __restrict__ yh,
                          __half* __restrict__ yl) {
    int tok = blockIdx.x;
    const float* xr = x + (size_t)tok * HIDD;
    float s = 0.f;
    for (int i = threadIdx.x * 4; i < HIDD; i += blockDim.x * 4) {
        float4 v = *(const float4*)(xr + i);
        s += v.x * v.x + v.y * v.y + v.z * v.z + v.w * v.w;
    }
    __shared__ float red[32];
    for (int o = 16; o > 0; o >>= 1) s += __shfl_xor_sync(0xffffffffu, s, o);
    if ((threadIdx.x & 31) == 0) red[threadIdx.x >> 5] = s;
    __syncthreads();
    if (threadIdx.x < 32) {
        float v = (threadIdx.x < (blockDim.x >> 5)) ? red[threadIdx.x] : 0.f;
        for (int o = 4; o > 0; o >>= 1) v += __shfl_xor_sync(0xffffffffu, v, o);
        if (threadIdx.x == 0) red[0] = rsqrtf(v / (float)HIDD + EPS);
    }
    __syncthreads();
    float sc = red[0];
    for (int i = threadIdx.x * 4; i < HIDD; i += blockDim.x * 4) {
        float4 v = *(const float4*)(xr + i);
        float4 wv = *(const float4*)(w + i);
        float4 o;
        o.x = v.x * sc * wv.x; o.y = v.y * sc * wv.y;
        o.z = v.z * sc * wv.z; o.w = v.w * sc * wv.w;
        size_t idx = (size_t)tok * HIDD + i;
        if (yf) *(float4*)(yf + idx) = o;
        if (yh) {
            __half h0, l0h, h1, l1h, h2, l2h, h3, l3h;
            split16(o.x, h0, l0h); split16(o.y, h1, l1h);
            split16(o.z, h2, l2h); split16(o.w, h3, l3h);
            *(__half2*)(yh + idx) = __halves2half2(h0, h1);
            *(__half2*)(yh + idx + 2) = __halves2half2(h2, h3);
            if (yl) {
                *(__half2*)(yl + idx) = __halves2half2(l0h, l1h);
                *(__half2*)(yl + idx + 2) = __halves2half2(l2h, l3h);
            }
        }
    }
}

// ---------------- weight cvt (wide, streaming) ----------------
__device__ __forceinline__ uint32_t packsplit_h(float a, float b) {
    __half2 t = __floats2half2_rn(a, b);
    return *(uint32_t*)&t;
}

// split cvt: 8 floats/thread -> h uint4 + l uint4
__global__ void cvt16_k(const float* __restrict__ s, __half* __restrict__ h,
                        __half* __restrict__ l, size_t n) {
    size_t i = ((size_t)blockIdx.x * blockDim.x + threadIdx.x) * 8;
    if (i >= n) return;
    float4 v0 = __ldcs((const float4*)(s + i));
    float4 v1 = __ldcs((const float4*)(s + i + 4));
    float f[8] = {v0.x, v0.y, v0.z, v0.w, v1.x, v1.y, v1.z, v1.w};
    uint32_t hw[4], lw[4];
#pragma unroll
    for (int j = 0; j < 4; j++) {
        __half ha, la, hb, lb;
        split16(f[2 * j], ha, la); split16(f[2 * j + 1], hb, lb);
        __half2 hh = __halves2half2(ha, hb), ll = __halves2half2(la, lb);
        hw[j] = *(uint32_t*)&hh; lw[j] = *(uint32_t*)&ll;
    }
    __stcs((uint4*)(h + i), make_uint4(hw[0], hw[1], hw[2], hw[3]));
    __stcs((uint4*)(l + i), make_uint4(lw[0], lw[1], lw[2], lw[3]));
}

// plain cvt: 8 floats/thread -> uint4
__global__ void cvt16h_k(const float* __restrict__ s, __half* __restrict__ h, size_t n) {
    size_t i = ((size_t)blockIdx.x * blockDim.x + threadIdx.x) * 8;
    if (i >= n) return;
    float4 v0 = __ldcs((const float4*)(s + i));
    float4 v1 = __ldcs((const float4*)(s + i + 4));
    __stcs((uint4*)(h + i),
           make_uint4(packsplit_h(v0.x, v0.y), packsplit_h(v0.z, v0.w),
                      packsplit_h(v1.x, v1.y), packsplit_h(v1.z, v1.w)));
}

// interleaved cvt for gate/up: src row j (within expert) -> dst row 2j+off
__global__ void cvt16h_il_k(const float* __restrict__ s, __half* __restrict__ h,
                            size_t n, int off) {
    size_t i = ((size_t)blockIdx.x * blockDim.x + threadIdx.x) * 8;
    if (i >= n) return;
    size_t row = i / HIDD;               // global row among NE*INTER
    size_t e = row / INTER, j = row % INTER;
    size_t dst = (e * 2 * INTER + 2 * j + (size_t)off) * HIDD + (i % HIDD);
    float4 v0 = __ldcs((const float4*)(s + i));
    float4 v1 = __ldcs((const float4*)(s + i + 4));
    __stcs((uint4*)(h + dst),
           make_uint4(packsplit_h(v0.x, v0.y), packsplit_h(v0.z, v0.w),
                      packsplit_h(v1.x, v1.y), packsplit_h(v1.z, v1.w)));
}

// ---------------- router ----------------
__global__ void zero_cnt_k() { if (threadIdx.x < NE) g_cnt[threadIdx.x] = 0; }

__global__ void router_k(const float* __restrict__ xn, const float* __restrict__ Wr) {
    const int tok = blockIdx.x;
    __shared__ float xs[HIDD];
    __shared__ float lg[NE];
    for (int i = threadIdx.x * 4; i < HIDD; i += blockDim.x * 4)
        *(float4*)(xs + i) = *(const float4*)(xn + (size_t)tok * HIDD + i);
    __syncthreads();
    const int w = threadIdx.x >> 5, lane = threadIdx.x & 31;
    const float* wr = Wr + (size_t)w * HIDD;
    float s = 0.f;
    for (int i = lane * 4; i < HIDD; i += 128) {
        float4 a = *(const float4*)(xs + i);
        float4 bb = *(const float4*)(wr + i);
        s += a.x * bb.x + a.y * bb.y + a.z * bb.z + a.w * bb.w;
    }
    for (int o = 16; o > 0; o >>= 1) s += __shfl_xor_sync(0xffffffffu, s, o);
    if (lane == 0) lg[w] = s;
    __syncthreads();
    if (threadIdx.x == 0) {
        float b1 = -INFINITY; int i1 = 0;
        for (int e = 0; e < NE; e++) if (lg[e] > b1) { b1 = lg[e]; i1 = e; }
        float b2 = -INFINITY; int i2 = (i1 == 0) ? 1 : 0;
        for (int e = 0; e < NE; e++) if (e != i1 && lg[e] > b2) { b2 = lg[e]; i2 = e; }
        float eo = expf(b2 - b1);
        float w1 = 1.f / (1.f + eo);
        float w2 = eo / (1.f + eo);
        int p1 = atomicAdd(&g_cnt[i1], 1);
        int p2 = atomicAdd(&g_cnt[i2], 1);
        g_gather[i1 * CAP + p1] = tok;
        g_gather[i2 * CAP + p2] = tok;
        g_slots[tok] = make_int2(i1 * CAP + p1, i2 * CAP + p2);
        g_wts[tok] = make_float2(w1, w2);
    }
}

// ---------------- final combine ----------------
__global__ void combine_k(const float* __restrict__ x2, float* __restrict__ out) {
    const int tok = blockIdx.x;
    const int2 sl = g_slots[tok];
    const float2 w = g_wts[tok];
    const float* y1 = g_yb + (size_t)sl.x * HIDD;
    const float* y2 = g_yb + (size_t)sl.y * HIDD;
    for (int i = threadIdx.x * 4; i < HIDD; i += blockDim.x * 4) {
        float4 a = *(const float4*)(x2 + (size_t)tok * HIDD + i);
        float4 b = *(const float4*)(y1 + i);
        float4 c = *(const float4*)(y2 + i);
        float4 o;
        o.x = a.x + w.x * b.x + w.y * c.x;
        o.y = a.y + w.x * b.y + w.y * c.y;
        o.z = a.z + w.x * b.z + w.y * c.z;
        o.w = a.w + w.x * b.w + w.y * c.w;
        *(float4*)(out + (size_t)tok * HIDD + i) = o;
    }
}

// ---------------- launch ----------------
extern "C" void kernel_launch(void* const* d_in, const int* in_sizes, int n_in,
                              void* d_out, int out_size) {
    (void)in_sizes; (void)n_in; (void)out_size;
    const float* x    = (const float*)d_in[0];
    const float* Wq   = (const float*)d_in[1];
    const float* Wk   = (const float*)d_in[2];
    const float* Wv   = (const float*)d_in[3];
    const float* Wo   = (const float*)d_in[4];
    const float* wln1 = (const float*)d_in[5];
    const float* wln2 = (const float*)d_in[6];
    const float* Wr   = (const float*)d_in[7];
    const float* Wg   = (const float*)d_in[8];
    const float* Wu   = (const float*)d_in[9];
    const float* Wd   = (const float*)d_in[10];
    float* out = (float*)d_out;

    void* p;
#define SYM(var, sym) cudaGetSymbolAddress(&p, sym); var = (decltype(var))p
    __half *xn1h, *xn1l, *qkvh, *qkvl, *atth, *attl, *wqkvh, *wqkvl, *woh, *wol;
    __half *xn2h, *wguh, *wdh, *acth;
    float *x2, *xn2, *yb;
    SYM(xn1h, g_xn1h); SYM(xn1l, g_xn1l);
    SYM(qkvh, g_qkvh); SYM(qkvl, g_qkvl);
    SYM(atth, g_atth); SYM(attl, g_attl);
    SYM(wqkvh, g_wqkvh); SYM(wqkvl, g_wqkvl);
    SYM(woh, g_woh); SYM(wol, g_wol);
    SYM(xn2h, g_xn2h); SYM(wguh, g_wguh); SYM(wdh, g_wdh);
    SYM(acth, g_acth);
    SYM(x2, g_x2); SYM(xn2, g_xn2); SYM(yb, g_yb);
#undef SYM

    const int split_smem  = 8 * HTILE * 2;   // 81920
    const int single_smem = 4 * HTILE * 2;   // 40960
    cudaFuncSetAttribute((const void*)hgemm<true,  false, false, true,  false>,
                         cudaFuncAttributeMaxDynamicSharedMemorySize, split_smem);
    cudaFuncSetAttribute((const void*)hgemm<true,  false, false, false, false>,
                         cudaFuncAttributeMaxDynamicSharedMemorySize, split_smem);
    cudaFuncSetAttribute((const void*)hgemm<false, true,  true,  false, true>,
                         cudaFuncAttributeMaxDynamicSharedMemorySize, single_smem);
    cudaFuncSetAttribute((const void*)hgemm<false, true,  false, false, false>,
                         cudaFuncAttributeMaxDynamicSharedMemorySize, single_smem);
    cudaFuncSetAttribute(flash_mma_k, cudaFuncAttributeMaxDynamicSharedMemorySize, FLASH_SMEM);

    const size_t HH = (size_t)HIDD * HIDD;
    const size_t EIH = (size_t)NE * INTER * HIDD;

    // weight prepass (wide streaming)
    cvt16_k<<<(unsigned)(HH / 2048), 256>>>(Wq, wqkvh, wqkvl, HH);
    cvt16_k<<<(unsigned)(HH / 2048), 256>>>(Wk, wqkvh + HH, wqkvl + HH, HH);
    cvt16_k<<<(unsigned)(HH / 2048), 256>>>(Wv, wqkvh + 2 * HH, wqkvl + 2 * HH, HH);
    cvt16_k<<<(unsigned)(HH / 2048), 256>>>(Wo, woh, wol, HH);
    cvt16h_il_k<<<(unsigned)(EIH / 2048), 256>>>(Wg, wguh, EIH, 0);
    cvt16h_il_k<<<(unsigned)(EIH / 2048), 256>>>(Wu, wguh, EIH, 1);
    cvt16h_k<<<(unsigned)(EIH / 2048), 256>>>(Wd, wdh, EIH);

    // 1) ln1 -> fp16 h/l
    rmsnorm_k<<<T_TOK, 256>>>(x, wln1, nullptr, xn1h, xn1l);
    // 2) fused QKV projection (split, fp16 h/l epilogue)
    hgemm<true, false, false, true, false><<<dim3(QKVW / HBN, T_TOK / HBM), 256, split_smem>>>(
        xn1h, xn1l, wqkvh, wqkvl, nullptr, nullptr, qkvh, qkvl, T_TOK, QKVW, HIDD, 0, 0, 0);
    // 3) flash attention
    flash_mma_k<<<dim3(SEQ / 64, NH, NB), 128, FLASH_SMEM>>>();
    // 4) O projection + residual (split, fp32 out)
    hgemm<true, false, false, false, false><<<dim3(HIDD / HBN, T_TOK / HBM), 256, split_smem>>>(
        atth, attl, woh, wol, x, x2, nullptr, nullptr, T_TOK, HIDD, HIDD, 0, 0, 0);
    // 5) ln2 -> fp32 (router) + fp16 (experts)
    rmsnorm_k<<<T_TOK, 256>>>(x2, wln2, xn2, xn2h, nullptr);
    // 6) routing
    zero_cnt_k<<<1, 32>>>();
    router_k<<<T_TOK, 256>>>(xn2, Wr);
    // 7) fused gate+up GEMM with SwiGLU epilogue -> acth (fp16)
    hgemm<false, true, true, false, true><<<dim3(2 * INTER / HBN, CAP / HBM, NE), 256, single_smem>>>(
        xn2h, nullptr, wguh, nullptr, nullptr, nullptr, acth, nullptr,
        0, 2 * INTER, HIDD, 0, (size_t)2 * INTER * HIDD, (size_t)CAP * INTER);
    // 8) down GEMM
    hgemm<false, true, false, false, false><<<dim3(HIDD / HBN, CAP / HBM, NE), 256, single_smem>>>(
        acth, nullptr, wdh, nullptr, nullptr, yb, nullptr, nullptr,
        0, HIDD, INTER, (size_t)CAP * INTER, (size_t)HIDD * INTER, (size_t)CAP * HIDD);
    // 9) combine + final residual
    combine_k<<<T_TOK, 256>>>(x2, out);
}